// round 1
// baseline (speedup 1.0000x reference)
#include <cuda_runtime.h>
#include <math_constants.h>

#define Bn 8
#define Cn 64
#define Hn 128
#define Wn 128

// Scratch (device-global; no allocation allowed)
__device__ float g_q[Bn*Hn*Wn*Cn];          // [b][h][w][c]
__device__ float g_k[Bn*Hn*Wn*Cn];
__device__ float g_v[Bn*Hn*Wn*Cn];
__device__ float g_att[Bn*Hn*Wn*2*Hn];      // [b][h][w][256] logits -> att (in-place)
__device__ float g_oH[Bn*Hn*Wn*Cn];         // [b][w][h][c]
__device__ float g_oW[Bn*Hn*Wn*Cn];         // [b][h][w][c]
__device__ float g_wt[3*3*3*Cn*Cn];         // [conv][ky][kx][ci][co]

// ---------------------------------------------------------------------------
// Weight re-layout: OIHW -> [conv][ky][kx][ci][co]
// ---------------------------------------------------------------------------
__global__ void prep_w_k(const float* __restrict__ Wq,
                         const float* __restrict__ Wk,
                         const float* __restrict__ Wv)
{
    int i = blockIdx.x*blockDim.x + threadIdx.x;
    if (i >= 3*3*3*Cn*Cn) return;
    int co = i % Cn; int t = i / Cn;
    int ci = t % Cn; t /= Cn;
    int kx = t % 3;  t /= 3;
    int ky = t % 3;  t /= 3;
    int conv = t;
    const float* Ws = (conv == 0) ? Wq : ((conv == 1) ? Wk : Wv);
    g_wt[i] = Ws[((co*Cn + ci)*3 + ky)*3 + kx];
}

// ---------------------------------------------------------------------------
// 3x3 conv, pad=1: out[b][h][w][co] = bias[co] + sum_{ci,ky,kx} x*W
// Block = (b,h) row. 256 threads: 16 w-groups x 16 co-groups, 8w x 4co tile.
// ---------------------------------------------------------------------------
__global__ __launch_bounds__(256) void conv3x3_k(const float* __restrict__ x,
                                                 const float* __restrict__ bias,
                                                 int sel)
{
    __shared__ float xrow[Cn][132];   // [ci][j], j=0..129 maps w=j-1
    const int h = blockIdx.x, b = blockIdx.y;
    const int tx = threadIdx.x & 15, ty = threadIdx.x >> 4;
    const int w0 = tx*8, co0 = ty*4;

    const float* wt = g_wt + sel*9*Cn*Cn;
    float* out = (sel == 0) ? g_q : ((sel == 1) ? g_k : g_v);

    float acc[8][4];
    const float4 bv = *(const float4*)&bias[co0];
#pragma unroll
    for (int j = 0; j < 8; j++) {
        acc[j][0] = bv.x; acc[j][1] = bv.y; acc[j][2] = bv.z; acc[j][3] = bv.w;
    }

    for (int ky = 0; ky < 3; ky++) {
        const int row = h + ky - 1;
        __syncthreads();
        if ((unsigned)row < Hn) {
            const float* xr = x + ((size_t)b*Cn*Hn + row)*Wn;
            for (int i = threadIdx.x; i < Cn*130; i += 256) {
                int ci = i / 130, j = i - ci*130;
                int ww = j - 1;
                xrow[ci][j] = ((unsigned)ww < Wn) ? xr[(size_t)ci*Hn*Wn + ww] : 0.f;
            }
        } else {
            for (int i = threadIdx.x; i < Cn*130; i += 256) {
                int ci = i / 130, j = i - ci*130;
                xrow[ci][j] = 0.f;
            }
        }
        __syncthreads();
        if ((unsigned)row >= Hn) continue;

        const float* wky = wt + ky*3*Cn*Cn;
#pragma unroll 2
        for (int ci = 0; ci < Cn; ci++) {
            float aw[10];
            float4 t0 = *(const float4*)&xrow[ci][w0];
            float4 t1 = *(const float4*)&xrow[ci][w0+4];
            aw[0]=t0.x; aw[1]=t0.y; aw[2]=t0.z; aw[3]=t0.w;
            aw[4]=t1.x; aw[5]=t1.y; aw[6]=t1.z; aw[7]=t1.w;
            aw[8]=xrow[ci][w0+8]; aw[9]=xrow[ci][w0+9];
#pragma unroll
            for (int kx = 0; kx < 3; kx++) {
                const float4 wv = __ldg((const float4*)&wky[(kx*Cn + ci)*Cn + co0]);
#pragma unroll
                for (int j = 0; j < 8; j++) {
                    acc[j][0] += aw[j+kx]*wv.x;
                    acc[j][1] += aw[j+kx]*wv.y;
                    acc[j][2] += aw[j+kx]*wv.z;
                    acc[j][3] += aw[j+kx]*wv.w;
                }
            }
        }
    }

    float* op = out + ((size_t)(b*Hn + h)*Wn)*Cn;
#pragma unroll
    for (int j = 0; j < 8; j++) {
        *(float4*)&op[(w0+j)*Cn + co0] =
            make_float4(acc[j][0], acc[j][1], acc[j][2], acc[j][3]);
    }
}

// ---------------------------------------------------------------------------
// eH logits: block (w,b). C[h][g] = sum_c q[b,h,w,c]*k[b,g,w,c]; diag -> -inf
// writes att[b][h][w][g]
// ---------------------------------------------------------------------------
__global__ __launch_bounds__(256) void eh_logits_k()
{
    __shared__ float qs[Hn][17];     // [h][cl]
    __shared__ float kst[16][132];   // [cl][g]
    const int w = blockIdx.x, b = blockIdx.y;
    const int tx = threadIdx.x & 15, ty = threadIdx.x >> 4;
    const int g0 = tx*8, h0 = ty*8;
    float acc[8][8] = {};
    const float* qb = g_q + ((size_t)b*Hn*Wn + w)*Cn;
    const float* kb = g_k + ((size_t)b*Hn*Wn + w)*Cn;

    for (int cc = 0; cc < Cn; cc += 16) {
        __syncthreads();
        for (int i = threadIdx.x; i < Hn*16; i += 256) {
            int r = i >> 4, cl = i & 15;
            float qv = qb[(size_t)r*Wn*Cn + cc + cl];
            float kv = kb[(size_t)r*Wn*Cn + cc + cl];
            qs[r][cl]  = qv;
            kst[cl][r] = kv;
        }
        __syncthreads();
#pragma unroll
        for (int kk = 0; kk < 16; kk++) {
            float aa[8], bb[8];
#pragma unroll
            for (int j = 0; j < 8; j++) aa[j] = qs[h0+j][kk];
            float4 b0 = *(const float4*)&kst[kk][g0];
            float4 b1 = *(const float4*)&kst[kk][g0+4];
            bb[0]=b0.x; bb[1]=b0.y; bb[2]=b0.z; bb[3]=b0.w;
            bb[4]=b1.x; bb[5]=b1.y; bb[6]=b1.z; bb[7]=b1.w;
#pragma unroll
            for (int j = 0; j < 8; j++)
#pragma unroll
                for (int l = 0; l < 8; l++) acc[j][l] += aa[j]*bb[l];
        }
    }

#pragma unroll
    for (int j = 0; j < 8; j++) {
        int h = h0 + j;
        float* row = g_att + ((size_t)(b*Hn + h)*Wn + w)*256 + g0;
#pragma unroll
        for (int l = 0; l < 8; l += 4) {
            float4 r;
            r.x = (h == g0+l  ) ? -CUDART_INF_F : acc[j][l];
            r.y = (h == g0+l+1) ? -CUDART_INF_F : acc[j][l+1];
            r.z = (h == g0+l+2) ? -CUDART_INF_F : acc[j][l+2];
            r.w = (h == g0+l+3) ? -CUDART_INF_F : acc[j][l+3];
            *(float4*)&row[l] = r;
        }
    }
}

// ---------------------------------------------------------------------------
// eW logits: block (h,b). C[w][g] = sum_c q[b,h,w,c]*k[b,h,g,c]
// writes att[b][h][w][128+g]
// ---------------------------------------------------------------------------
__global__ __launch_bounds__(256) void ew_logits_k()
{
    __shared__ float qs[Wn][17];
    __shared__ float kst[16][132];
    const int h = blockIdx.x, b = blockIdx.y;
    const int tx = threadIdx.x & 15, ty = threadIdx.x >> 4;
    const int g0 = tx*8, w0 = ty*8;
    float acc[8][8] = {};
    const float* qb = g_q + ((size_t)(b*Hn + h)*Wn)*Cn;
    const float* kb = g_k + ((size_t)(b*Hn + h)*Wn)*Cn;

    for (int cc = 0; cc < Cn; cc += 16) {
        __syncthreads();
        for (int i = threadIdx.x; i < Wn*16; i += 256) {
            int r = i >> 4, cl = i & 15;
            qs[r][cl]  = qb[r*Cn + cc + cl];
            kst[cl][r] = kb[r*Cn + cc + cl];
        }
        __syncthreads();
#pragma unroll
        for (int kk = 0; kk < 16; kk++) {
            float aa[8], bb[8];
#pragma unroll
            for (int j = 0; j < 8; j++) aa[j] = qs[w0+j][kk];
            float4 b0 = *(const float4*)&kst[kk][g0];
            float4 b1 = *(const float4*)&kst[kk][g0+4];
            bb[0]=b0.x; bb[1]=b0.y; bb[2]=b0.z; bb[3]=b0.w;
            bb[4]=b1.x; bb[5]=b1.y; bb[6]=b1.z; bb[7]=b1.w;
#pragma unroll
            for (int j = 0; j < 8; j++)
#pragma unroll
                for (int l = 0; l < 8; l++) acc[j][l] += aa[j]*bb[l];
        }
    }

#pragma unroll
    for (int j = 0; j < 8; j++) {
        float* row = g_att + ((size_t)(b*Hn + h)*Wn + (w0+j))*256 + 128 + g0;
        *(float4*)&row[0] = make_float4(acc[j][0], acc[j][1], acc[j][2], acc[j][3]);
        *(float4*)&row[4] = make_float4(acc[j][4], acc[j][5], acc[j][6], acc[j][7]);
    }
}

// ---------------------------------------------------------------------------
// Softmax over the 256 logits per pixel (warp per pixel), in place.
// ---------------------------------------------------------------------------
__global__ __launch_bounds__(256) void softmax_k()
{
    int p = (blockIdx.x << 3) + (threadIdx.x >> 5);
    int lane = threadIdx.x & 31;
    float* row = g_att + (size_t)p*256;
    float4 v0 = *(float4*)&row[lane*8];
    float4 v1 = *(float4*)&row[lane*8 + 4];
    float m = fmaxf(fmaxf(fmaxf(v0.x,v0.y), fmaxf(v0.z,v0.w)),
                    fmaxf(fmaxf(v1.x,v1.y), fmaxf(v1.z,v1.w)));
#pragma unroll
    for (int o = 16; o; o >>= 1) m = fmaxf(m, __shfl_xor_sync(~0u, m, o));
    float e[8];
    e[0]=__expf(v0.x-m); e[1]=__expf(v0.y-m); e[2]=__expf(v0.z-m); e[3]=__expf(v0.w-m);
    e[4]=__expf(v1.x-m); e[5]=__expf(v1.y-m); e[6]=__expf(v1.z-m); e[7]=__expf(v1.w-m);
    float s = (e[0]+e[1])+(e[2]+e[3])+((e[4]+e[5])+(e[6]+e[7]));
#pragma unroll
    for (int o = 16; o; o >>= 1) s += __shfl_xor_sync(~0u, s, o);
    float r = 1.0f / s;
    *(float4*)&row[lane*8]     = make_float4(e[0]*r, e[1]*r, e[2]*r, e[3]*r);
    *(float4*)&row[lane*8 + 4] = make_float4(e[4]*r, e[5]*r, e[6]*r, e[7]*r);
}

// ---------------------------------------------------------------------------
// out_W: block (h,b). C[w][c] = sum_g attW[w][g] * v[b,h,g,c] -> oW[b][h][w][c]
// ---------------------------------------------------------------------------
__global__ __launch_bounds__(256) void out_w_k()
{
    __shared__ float as[Wn][17];   // [w][kl]
    __shared__ float vs[16][68];   // [kl][c]
    const int h = blockIdx.x, b = blockIdx.y;
    const int tx = threadIdx.x & 15, ty = threadIdx.x >> 4;
    const int c0 = tx*4, w0 = ty*8;
    float acc[8][4] = {};
    const float* ab = g_att + ((size_t)(b*Hn + h)*Wn)*256 + 128;
    const float* vb = g_v   + ((size_t)(b*Hn + h)*Wn)*Cn;

    for (int gc = 0; gc < Hn; gc += 16) {
        __syncthreads();
        for (int i = threadIdx.x; i < Wn*16; i += 256) {
            int r = i >> 4, kl = i & 15;
            as[r][kl] = ab[(size_t)r*256 + gc + kl];
        }
        for (int i = threadIdx.x; i < 16*Cn; i += 256) {
            int kl = i >> 6, c = i & 63;
            vs[kl][c] = vb[(gc + kl)*Cn + c];
        }
        __syncthreads();
#pragma unroll
        for (int kk = 0; kk < 16; kk++) {
            float aa[8];
#pragma unroll
            for (int j = 0; j < 8; j++) aa[j] = as[w0+j][kk];
            float4 bv = *(const float4*)&vs[kk][c0];
#pragma unroll
            for (int j = 0; j < 8; j++) {
                acc[j][0] += aa[j]*bv.x; acc[j][1] += aa[j]*bv.y;
                acc[j][2] += aa[j]*bv.z; acc[j][3] += aa[j]*bv.w;
            }
        }
    }
    float* op = g_oW + ((size_t)(b*Hn + h)*Wn)*Cn;
#pragma unroll
    for (int j = 0; j < 8; j++)
        *(float4*)&op[(w0+j)*Cn + c0] =
            make_float4(acc[j][0], acc[j][1], acc[j][2], acc[j][3]);
}

// ---------------------------------------------------------------------------
// out_H: block (w,b). C[h][c] = sum_g attH[h][g] * v[b,g,w,c] -> oH[b][w][h][c]
// ---------------------------------------------------------------------------
__global__ __launch_bounds__(256) void out_h_k()
{
    __shared__ float as[Hn][17];
    __shared__ float vs[16][68];
    const int w = blockIdx.x, b = blockIdx.y;
    const int tx = threadIdx.x & 15, ty = threadIdx.x >> 4;
    const int c0 = tx*4, h0 = ty*8;
    float acc[8][4] = {};
    const float* ab = g_att + ((size_t)b*Hn*Wn + w)*256;
    const float* vb = g_v   + ((size_t)b*Hn*Wn + w)*Cn;

    for (int gc = 0; gc < Hn; gc += 16) {
        __syncthreads();
        for (int i = threadIdx.x; i < Hn*16; i += 256) {
            int r = i >> 4, kl = i & 15;
            as[r][kl] = ab[(size_t)r*Wn*256 + gc + kl];
        }
        for (int i = threadIdx.x; i < 16*Cn; i += 256) {
            int kl = i >> 6, c = i & 63;
            vs[kl][c] = vb[(size_t)(gc + kl)*Wn*Cn + c];
        }
        __syncthreads();
#pragma unroll
        for (int kk = 0; kk < 16; kk++) {
            float aa[8];
#pragma unroll
            for (int j = 0; j < 8; j++) aa[j] = as[h0+j][kk];
            float4 bv = *(const float4*)&vs[kk][c0];
#pragma unroll
            for (int j = 0; j < 8; j++) {
                acc[j][0] += aa[j]*bv.x; acc[j][1] += aa[j]*bv.y;
                acc[j][2] += aa[j]*bv.z; acc[j][3] += aa[j]*bv.w;
            }
        }
    }
    float* op = g_oH + ((size_t)(b*Wn + w)*Hn)*Cn;
#pragma unroll
    for (int j = 0; j < 8; j++)
        *(float4*)&op[(h0+j)*Cn + c0] =
            make_float4(acc[j][0], acc[j][1], acc[j][2], acc[j][3]);
}

// ---------------------------------------------------------------------------
// Final: out[b][c][h][w] = gamma*(oH[b][w][h][c] + oW[b][h][w][c]) + x
// Tiled transpose so both read and write are coalesced.
// ---------------------------------------------------------------------------
__global__ __launch_bounds__(256) void final_k(const float* __restrict__ x,
                                               const float* __restrict__ gamma,
                                               float* __restrict__ out)
{
    __shared__ float s[Cn][33];
    const int w0 = blockIdx.x*32, h = blockIdx.y, b = blockIdx.z;
    const float g = gamma[0];
    for (int i = threadIdx.x; i < 32*Cn; i += 256) {
        int wl = i >> 6, c = i & 63;
        float a = g_oH[(((size_t)b*Wn + (w0+wl))*Hn + h)*Cn + c];
        float d = g_oW[(((size_t)b*Hn + h)*Wn + (w0+wl))*Cn + c];
        s[c][wl] = g*(a + d);
    }
    __syncthreads();
    for (int i = threadIdx.x; i < Cn*32; i += 256) {
        int c = i >> 5, wl = i & 31;
        size_t idx = (((size_t)b*Cn + c)*Hn + h)*Wn + w0 + wl;
        out[idx] = s[c][wl] + x[idx];
    }
}

// ---------------------------------------------------------------------------
extern "C" void kernel_launch(void* const* d_in, const int* in_sizes, int n_in,
                              void* d_out, int out_size)
{
    (void)in_sizes; (void)n_in; (void)out_size;
    const float* x     = (const float*)d_in[0];
    const float* Wq    = (const float*)d_in[1];
    const float* bq    = (const float*)d_in[2];
    const float* Wk    = (const float*)d_in[3];
    const float* bk    = (const float*)d_in[4];
    const float* Wv    = (const float*)d_in[5];
    const float* bv    = (const float*)d_in[6];
    const float* gamma = (const float*)d_in[7];
    float* out = (float*)d_out;

    prep_w_k<<<(3*3*3*Cn*Cn + 255)/256, 256>>>(Wq, Wk, Wv);

    dim3 grid_bh(Hn, Bn);   // (h, b)
    dim3 grid_bw(Wn, Bn);   // (w, b)
    conv3x3_k<<<grid_bh, 256>>>(x, bq, 0);
    conv3x3_k<<<grid_bh, 256>>>(x, bk, 1);
    conv3x3_k<<<grid_bh, 256>>>(x, bv, 2);

    eh_logits_k<<<grid_bw, 256>>>();
    ew_logits_k<<<grid_bh, 256>>>();

    softmax_k<<<(Bn*Hn*Wn)/8, 256>>>();

    out_h_k<<<grid_bw, 256>>>();
    out_w_k<<<grid_bh, 256>>>();

    dim3 grid_fin(Wn/32, Hn, Bn);
    final_k<<<grid_fin, 256>>>(x, gamma, out);
}

// round 2
// speedup vs baseline: 1.0938x; 1.0938x over previous
#include <cuda_runtime.h>
#include <math_constants.h>

#define Bn 8
#define Cn 64
#define Hn 128
#define Wn 128

// Scratch (device-global; no allocation allowed)
__device__ float g_q[Bn*Hn*Wn*Cn];          // [b][h][w][c]
__device__ float g_k[Bn*Hn*Wn*Cn];
__device__ float g_v[Bn*Hn*Wn*Cn];
__device__ float g_att[Bn*Hn*Wn*2*Hn];      // [b][h][w][256] logits -> att (in-place)
__device__ float g_oH[Bn*Hn*Wn*Cn];         // [b][w][h][c]
__device__ float g_oW[Bn*Hn*Wn*Cn];         // [b][h][w][c]
__device__ float g_wt[3*3*3*Cn*Cn];         // [conv][ky][kx][ci][co]

// ---------------------------------------------------------------------------
// Packed f32x2 helpers (Blackwell FFMA2 — 2 fp32 FMA per issue)
// ---------------------------------------------------------------------------
typedef unsigned long long u64;

__device__ __forceinline__ u64 pack2(float lo, float hi) {
    u64 r;
    asm("mov.b64 %0, {%1, %2};" : "=l"(r) : "f"(lo), "f"(hi));
    return r;
}
__device__ __forceinline__ u64 bcast2(float v) {
    u64 r;
    asm("mov.b64 %0, {%1, %1};" : "=l"(r) : "f"(v));
    return r;
}
__device__ __forceinline__ u64 ffma2(u64 a, u64 b, u64 c) {
    u64 d;
    asm("fma.rn.f32x2 %0, %1, %2, %3;" : "=l"(d) : "l"(a), "l"(b), "l"(c));
    return d;
}
__device__ __forceinline__ float2 unpack2(u64 v) {
    float2 f;
    asm("mov.b64 {%0, %1}, %2;" : "=f"(f.x), "=f"(f.y) : "l"(v));
    return f;
}

// ---------------------------------------------------------------------------
// Weight re-layout: OIHW -> [conv][ky][kx][ci][co]
// ---------------------------------------------------------------------------
__global__ void prep_w_k(const float* __restrict__ Wq,
                         const float* __restrict__ Wk,
                         const float* __restrict__ Wv)
{
    int i = blockIdx.x*blockDim.x + threadIdx.x;
    if (i >= 3*3*3*Cn*Cn) return;
    int co = i % Cn; int t = i / Cn;
    int ci = t % Cn; t /= Cn;
    int kx = t % 3;  t /= 3;
    int ky = t % 3;  t /= 3;
    int conv = t;
    const float* Ws = (conv == 0) ? Wq : ((conv == 1) ? Wk : Wv);
    g_wt[i] = Ws[((co*Cn + ci)*3 + ky)*3 + kx];
}

// ---------------------------------------------------------------------------
// 3x3 conv, pad=1: out[b][h][w][co] = bias[co] + sum_{ci,ky,kx} x*W
// Block = (b,h,sel). 256 threads: 16 w-groups x 16 co-groups, 8w x 4co tile.
// Accumulators packed as f32x2 co-pairs -> FFMA2.
// ---------------------------------------------------------------------------
__global__ __launch_bounds__(256) void conv3x3_k(const float* __restrict__ x,
                                                 const float* __restrict__ bq,
                                                 const float* __restrict__ bk,
                                                 const float* __restrict__ bv)
{
    __shared__ float xrow[Cn][132];   // [ci][j], j=0..129 maps w=j-1
    const int h = blockIdx.x, b = blockIdx.y, sel = blockIdx.z;
    const int tx = threadIdx.x & 15, ty = threadIdx.x >> 4;
    const int wid = threadIdx.x >> 5, lane = threadIdx.x & 31;
    const int w0 = tx*8, co0 = ty*4;

    const float* wt = g_wt + sel*9*Cn*Cn;
    const float* bias = (sel == 0) ? bq : ((sel == 1) ? bk : bv);
    float* out = (sel == 0) ? g_q : ((sel == 1) ? g_k : g_v);

    u64 acc[8][2];
    {
        const float4 bv4 = *(const float4*)&bias[co0];
        const u64 b0 = pack2(bv4.x, bv4.y), b1 = pack2(bv4.z, bv4.w);
#pragma unroll
        for (int j = 0; j < 8; j++) { acc[j][0] = b0; acc[j][1] = b1; }
    }

    for (int ky = 0; ky < 3; ky++) {
        const int row = h + ky - 1;
        __syncthreads();
        if ((unsigned)row < Hn) {
            const float* xr = x + ((size_t)b*Cn*Hn + row)*Wn;
            for (int ci = wid; ci < Cn; ci += 8)
                for (int j = lane; j < 130; j += 32) {
                    int ww = j - 1;
                    xrow[ci][j] = ((unsigned)ww < Wn) ? xr[(size_t)ci*Hn*Wn + ww] : 0.f;
                }
        } else {
            for (int ci = wid; ci < Cn; ci += 8)
                for (int j = lane; j < 130; j += 32)
                    xrow[ci][j] = 0.f;
        }
        __syncthreads();
        if ((unsigned)row >= Hn) continue;

        const float* wky = wt + ky*3*Cn*Cn;
#pragma unroll 2
        for (int ci = 0; ci < Cn; ci++) {
            float4 t0 = *(const float4*)&xrow[ci][w0];
            float4 t1 = *(const float4*)&xrow[ci][w0+4];
            float2 t2 = *(const float2*)&xrow[ci][w0+8];
            u64 aw2[10];
            aw2[0]=bcast2(t0.x); aw2[1]=bcast2(t0.y); aw2[2]=bcast2(t0.z); aw2[3]=bcast2(t0.w);
            aw2[4]=bcast2(t1.x); aw2[5]=bcast2(t1.y); aw2[6]=bcast2(t1.z); aw2[7]=bcast2(t1.w);
            aw2[8]=bcast2(t2.x); aw2[9]=bcast2(t2.y);
#pragma unroll
            for (int kx = 0; kx < 3; kx++) {
                const ulonglong2 wv = __ldg((const ulonglong2*)&wky[(kx*Cn + ci)*Cn + co0]);
#pragma unroll
                for (int j = 0; j < 8; j++) {
                    acc[j][0] = ffma2(aw2[j+kx], wv.x, acc[j][0]);
                    acc[j][1] = ffma2(aw2[j+kx], wv.y, acc[j][1]);
                }
            }
        }
    }

    float* op = out + ((size_t)(b*Hn + h)*Wn)*Cn;
#pragma unroll
    for (int j = 0; j < 8; j++) {
        float2 p0 = unpack2(acc[j][0]), p1 = unpack2(acc[j][1]);
        *(float4*)&op[(w0+j)*Cn + co0] = make_float4(p0.x, p0.y, p1.x, p1.y);
    }
}

// ---------------------------------------------------------------------------
// eH logits: block (w,b). C[h][g] = sum_c q[b,h,w,c]*k[b,g,w,c]; diag -> -inf
// writes att[b][h][w][g]
// ---------------------------------------------------------------------------
__global__ __launch_bounds__(256) void eh_logits_k()
{
    __shared__ float qs[Hn][17];     // [h][cl]
    __shared__ float kst[16][132];   // [cl][g]
    const int w = blockIdx.x, b = blockIdx.y;
    const int tx = threadIdx.x & 15, ty = threadIdx.x >> 4;
    const int g0 = tx*8, h0 = ty*8;
    u64 acc[8][4];
#pragma unroll
    for (int j = 0; j < 8; j++)
#pragma unroll
        for (int l = 0; l < 4; l++) acc[j][l] = 0ull;
    const float* qb = g_q + ((size_t)b*Hn*Wn + w)*Cn;
    const float* kb = g_k + ((size_t)b*Hn*Wn + w)*Cn;

    for (int cc = 0; cc < Cn; cc += 16) {
        __syncthreads();
        for (int i = threadIdx.x; i < Hn*16; i += 256) {
            int r = i >> 4, cl = i & 15;
            qs[r][cl]  = qb[(size_t)r*Wn*Cn + cc + cl];
            kst[cl][r] = kb[(size_t)r*Wn*Cn + cc + cl];
        }
        __syncthreads();
#pragma unroll
        for (int kk = 0; kk < 16; kk++) {
            u64 aa[8];
#pragma unroll
            for (int j = 0; j < 8; j++) aa[j] = bcast2(qs[h0+j][kk]);
            const ulonglong2 b01 = *(const ulonglong2*)&kst[kk][g0];
            const ulonglong2 b23 = *(const ulonglong2*)&kst[kk][g0+4];
#pragma unroll
            for (int j = 0; j < 8; j++) {
                acc[j][0] = ffma2(aa[j], b01.x, acc[j][0]);
                acc[j][1] = ffma2(aa[j], b01.y, acc[j][1]);
                acc[j][2] = ffma2(aa[j], b23.x, acc[j][2]);
                acc[j][3] = ffma2(aa[j], b23.y, acc[j][3]);
            }
        }
    }

#pragma unroll
    for (int j = 0; j < 8; j++) {
        int h = h0 + j;
        float* row = g_att + ((size_t)(b*Hn + h)*Wn + w)*256 + g0;
        float2 p0 = unpack2(acc[j][0]), p1 = unpack2(acc[j][1]);
        float2 p2 = unpack2(acc[j][2]), p3 = unpack2(acc[j][3]);
        float4 r0, r1;
        r0.x = (h == g0  ) ? -CUDART_INF_F : p0.x;
        r0.y = (h == g0+1) ? -CUDART_INF_F : p0.y;
        r0.z = (h == g0+2) ? -CUDART_INF_F : p1.x;
        r0.w = (h == g0+3) ? -CUDART_INF_F : p1.y;
        r1.x = (h == g0+4) ? -CUDART_INF_F : p2.x;
        r1.y = (h == g0+5) ? -CUDART_INF_F : p2.y;
        r1.z = (h == g0+6) ? -CUDART_INF_F : p3.x;
        r1.w = (h == g0+7) ? -CUDART_INF_F : p3.y;
        *(float4*)&row[0] = r0;
        *(float4*)&row[4] = r1;
    }
}

// ---------------------------------------------------------------------------
// eW logits: block (h,b). C[w][g] = sum_c q[b,h,w,c]*k[b,h,g,c]
// writes att[b][h][w][128+g]
// ---------------------------------------------------------------------------
__global__ __launch_bounds__(256) void ew_logits_k()
{
    __shared__ float qs[Wn][17];
    __shared__ float kst[16][132];
    const int h = blockIdx.x, b = blockIdx.y;
    const int tx = threadIdx.x & 15, ty = threadIdx.x >> 4;
    const int g0 = tx*8, w0 = ty*8;
    u64 acc[8][4];
#pragma unroll
    for (int j = 0; j < 8; j++)
#pragma unroll
        for (int l = 0; l < 4; l++) acc[j][l] = 0ull;
    const float* qb = g_q + ((size_t)(b*Hn + h)*Wn)*Cn;
    const float* kb = g_k + ((size_t)(b*Hn + h)*Wn)*Cn;

    for (int cc = 0; cc < Cn; cc += 16) {
        __syncthreads();
        for (int i = threadIdx.x; i < Wn*16; i += 256) {
            int r = i >> 4, cl = i & 15;
            qs[r][cl]  = qb[r*Cn + cc + cl];
            kst[cl][r] = kb[r*Cn + cc + cl];
        }
        __syncthreads();
#pragma unroll
        for (int kk = 0; kk < 16; kk++) {
            u64 aa[8];
#pragma unroll
            for (int j = 0; j < 8; j++) aa[j] = bcast2(qs[w0+j][kk]);
            const ulonglong2 b01 = *(const ulonglong2*)&kst[kk][g0];
            const ulonglong2 b23 = *(const ulonglong2*)&kst[kk][g0+4];
#pragma unroll
            for (int j = 0; j < 8; j++) {
                acc[j][0] = ffma2(aa[j], b01.x, acc[j][0]);
                acc[j][1] = ffma2(aa[j], b01.y, acc[j][1]);
                acc[j][2] = ffma2(aa[j], b23.x, acc[j][2]);
                acc[j][3] = ffma2(aa[j], b23.y, acc[j][3]);
            }
        }
    }

#pragma unroll
    for (int j = 0; j < 8; j++) {
        float* row = g_att + ((size_t)(b*Hn + h)*Wn + (w0+j))*256 + 128 + g0;
        float2 p0 = unpack2(acc[j][0]), p1 = unpack2(acc[j][1]);
        float2 p2 = unpack2(acc[j][2]), p3 = unpack2(acc[j][3]);
        *(float4*)&row[0] = make_float4(p0.x, p0.y, p1.x, p1.y);
        *(float4*)&row[4] = make_float4(p2.x, p2.y, p3.x, p3.y);
    }
}

// ---------------------------------------------------------------------------
// Softmax over the 256 logits per pixel (warp per pixel), in place.
// ---------------------------------------------------------------------------
__global__ __launch_bounds__(256) void softmax_k()
{
    int p = (blockIdx.x << 3) + (threadIdx.x >> 5);
    int lane = threadIdx.x & 31;
    float* row = g_att + (size_t)p*256;
    float4 v0 = *(float4*)&row[lane*8];
    float4 v1 = *(float4*)&row[lane*8 + 4];
    float m = fmaxf(fmaxf(fmaxf(v0.x,v0.y), fmaxf(v0.z,v0.w)),
                    fmaxf(fmaxf(v1.x,v1.y), fmaxf(v1.z,v1.w)));
#pragma unroll
    for (int o = 16; o; o >>= 1) m = fmaxf(m, __shfl_xor_sync(~0u, m, o));
    float e[8];
    e[0]=__expf(v0.x-m); e[1]=__expf(v0.y-m); e[2]=__expf(v0.z-m); e[3]=__expf(v0.w-m);
    e[4]=__expf(v1.x-m); e[5]=__expf(v1.y-m); e[6]=__expf(v1.z-m); e[7]=__expf(v1.w-m);
    float s = (e[0]+e[1])+(e[2]+e[3])+((e[4]+e[5])+(e[6]+e[7]));
#pragma unroll
    for (int o = 16; o; o >>= 1) s += __shfl_xor_sync(~0u, s, o);
    float r = 1.0f / s;
    *(float4*)&row[lane*8]     = make_float4(e[0]*r, e[1]*r, e[2]*r, e[3]*r);
    *(float4*)&row[lane*8 + 4] = make_float4(e[4]*r, e[5]*r, e[6]*r, e[7]*r);
}

// ---------------------------------------------------------------------------
// out_W: block (h,b). C[w][c] = sum_g attW[w][g] * v[b,h,g,c] -> oW[b][h][w][c]
// ---------------------------------------------------------------------------
__global__ __launch_bounds__(256) void out_w_k()
{
    __shared__ float as[Wn][17];   // [w][kl]
    __shared__ float vs[16][68];   // [kl][c]
    const int h = blockIdx.x, b = blockIdx.y;
    const int tx = threadIdx.x & 15, ty = threadIdx.x >> 4;
    const int c0 = tx*4, w0 = ty*8;
    u64 acc[8][2];
#pragma unroll
    for (int j = 0; j < 8; j++) { acc[j][0] = 0ull; acc[j][1] = 0ull; }
    const float* ab = g_att + ((size_t)(b*Hn + h)*Wn)*256 + 128;
    const float* vb = g_v   + ((size_t)(b*Hn + h)*Wn)*Cn;

    for (int gc = 0; gc < Hn; gc += 16) {
        __syncthreads();
        for (int i = threadIdx.x; i < Wn*16; i += 256) {
            int r = i >> 4, kl = i & 15;
            as[r][kl] = ab[(size_t)r*256 + gc + kl];
        }
        for (int i = threadIdx.x; i < 16*Cn; i += 256) {
            int kl = i >> 6, c = i & 63;
            vs[kl][c] = vb[(gc + kl)*Cn + c];
        }
        __syncthreads();
#pragma unroll
        for (int kk = 0; kk < 16; kk++) {
            const ulonglong2 bv = *(const ulonglong2*)&vs[kk][c0];
#pragma unroll
            for (int j = 0; j < 8; j++) {
                u64 aa = bcast2(as[w0+j][kk]);
                acc[j][0] = ffma2(aa, bv.x, acc[j][0]);
                acc[j][1] = ffma2(aa, bv.y, acc[j][1]);
            }
        }
    }
    float* op = g_oW + ((size_t)(b*Hn + h)*Wn)*Cn;
#pragma unroll
    for (int j = 0; j < 8; j++) {
        float2 p0 = unpack2(acc[j][0]), p1 = unpack2(acc[j][1]);
        *(float4*)&op[(w0+j)*Cn + c0] = make_float4(p0.x, p0.y, p1.x, p1.y);
    }
}

// ---------------------------------------------------------------------------
// out_H: block (w,b). C[h][c] = sum_g attH[h][g] * v[b,g,w,c] -> oH[b][w][h][c]
// ---------------------------------------------------------------------------
__global__ __launch_bounds__(256) void out_h_k()
{
    __shared__ float as[Hn][17];
    __shared__ float vs[16][68];
    const int w = blockIdx.x, b = blockIdx.y;
    const int tx = threadIdx.x & 15, ty = threadIdx.x >> 4;
    const int c0 = tx*4, h0 = ty*8;
    u64 acc[8][2];
#pragma unroll
    for (int j = 0; j < 8; j++) { acc[j][0] = 0ull; acc[j][1] = 0ull; }
    const float* ab = g_att + ((size_t)b*Hn*Wn + w)*256;
    const float* vb = g_v   + ((size_t)b*Hn*Wn + w)*Cn;

    for (int gc = 0; gc < Hn; gc += 16) {
        __syncthreads();
        for (int i = threadIdx.x; i < Hn*16; i += 256) {
            int r = i >> 4, kl = i & 15;
            as[r][kl] = ab[(size_t)r*Wn*256 + gc + kl];
        }
        for (int i = threadIdx.x; i < 16*Cn; i += 256) {
            int kl = i >> 6, c = i & 63;
            vs[kl][c] = vb[(size_t)(gc + kl)*Wn*Cn + c];
        }
        __syncthreads();
#pragma unroll
        for (int kk = 0; kk < 16; kk++) {
            const ulonglong2 bv = *(const ulonglong2*)&vs[kk][c0];
#pragma unroll
            for (int j = 0; j < 8; j++) {
                u64 aa = bcast2(as[h0+j][kk]);
                acc[j][0] = ffma2(aa, bv.x, acc[j][0]);
                acc[j][1] = ffma2(aa, bv.y, acc[j][1]);
            }
        }
    }
    float* op = g_oH + ((size_t)(b*Wn + w)*Hn)*Cn;
#pragma unroll
    for (int j = 0; j < 8; j++) {
        float2 p0 = unpack2(acc[j][0]), p1 = unpack2(acc[j][1]);
        *(float4*)&op[(h0+j)*Cn + c0] = make_float4(p0.x, p0.y, p1.x, p1.y);
    }
}

// ---------------------------------------------------------------------------
// Final: out[b][c][h][w] = gamma*(oH[b][w][h][c] + oW[b][h][w][c]) + x
// Tiled transpose so both read and write are coalesced.
// ---------------------------------------------------------------------------
__global__ __launch_bounds__(256) void final_k(const float* __restrict__ x,
                                               const float* __restrict__ gamma,
                                               float* __restrict__ out)
{
    __shared__ float s[Cn][33];
    const int w0 = blockIdx.x*32, h = blockIdx.y, b = blockIdx.z;
    const float g = gamma[0];
    for (int i = threadIdx.x; i < 32*Cn; i += 256) {
        int wl = i >> 6, c = i & 63;
        float a = g_oH[(((size_t)b*Wn + (w0+wl))*Hn + h)*Cn + c];
        float d = g_oW[(((size_t)b*Hn + h)*Wn + (w0+wl))*Cn + c];
        s[c][wl] = g*(a + d);
    }
    __syncthreads();
    for (int i = threadIdx.x; i < Cn*32; i += 256) {
        int c = i >> 5, wl = i & 31;
        size_t idx = (((size_t)b*Cn + c)*Hn + h)*Wn + w0 + wl;
        out[idx] = s[c][wl] + x[idx];
    }
}

// ---------------------------------------------------------------------------
extern "C" void kernel_launch(void* const* d_in, const int* in_sizes, int n_in,
                              void* d_out, int out_size)
{
    (void)in_sizes; (void)n_in; (void)out_size;
    const float* x     = (const float*)d_in[0];
    const float* Wq    = (const float*)d_in[1];
    const float* bq    = (const float*)d_in[2];
    const float* Wk    = (const float*)d_in[3];
    const float* bk    = (const float*)d_in[4];
    const float* Wv    = (const float*)d_in[5];
    const float* bv    = (const float*)d_in[6];
    const float* gamma = (const float*)d_in[7];
    float* out = (float*)d_out;

    prep_w_k<<<(3*3*3*Cn*Cn + 255)/256, 256>>>(Wq, Wk, Wv);

    dim3 grid_conv(Hn, Bn, 3);   // (h, b, sel)
    conv3x3_k<<<grid_conv, 256>>>(x, bq, bk, bv);

    dim3 grid_bh(Hn, Bn);   // (h, b)
    dim3 grid_bw(Wn, Bn);   // (w, b)
    eh_logits_k<<<grid_bw, 256>>>();
    ew_logits_k<<<grid_bh, 256>>>();

    softmax_k<<<(Bn*Hn*Wn)/8, 256>>>();

    out_h_k<<<grid_bw, 256>>>();
    out_w_k<<<grid_bh, 256>>>();

    dim3 grid_fin(Wn/32, Hn, Bn);
    final_k<<<grid_fin, 256>>>(x, gamma, out);
}

// round 4
// speedup vs baseline: 1.5686x; 1.4341x over previous
#include <cuda_runtime.h>
#include <cuda_bf16.h>
#include <math_constants.h>
#include <cstdint>

#define Bn 8
#define Cn 64
#define Hn 128
#define Wn 128

// ---------------------------------------------------------------------------
// Global scratch (no allocation allowed)
// ---------------------------------------------------------------------------
__device__ float g_q[Bn*Hn*Wn*Cn];          // [b][h][w][c]
__device__ float g_k[Bn*Hn*Wn*Cn];
__device__ float g_v[Bn*Hn*Wn*Cn];
__device__ float g_att[Bn*Hn*Wn*2*Hn];      // [b][h][w][256]
__device__ float g_oH[Bn*Hn*Wn*Cn];         // [b][w][h][c]
__device__ float g_oW[Bn*Hn*Wn*Cn];         // [b][h][w][c]
// bf16 hi/lo weight tiles, swizzled 128B rows:
// [sel][ky][kx][split] tiles of [64 co][64 ci], tile = 8192B
__device__ __align__(16) char g_wb16[3*3*3*2*8192];

// ---------------------------------------------------------------------------
// mma.sync / ldmatrix helpers (plain sm_80+ PTX — compiles for sm_103)
// ---------------------------------------------------------------------------
__device__ __forceinline__ uint32_t smem_u32(const void* p) {
    uint32_t a;
    asm("{ .reg .u64 t; cvta.to.shared.u64 t, %1; cvt.u32.u64 %0, t; }"
        : "=r"(a) : "l"(p));
    return a;
}
__device__ __forceinline__ void ldsm4(uint32_t* r, uint32_t addr) {
    asm volatile("ldmatrix.sync.aligned.m8n8.x4.shared.b16 {%0,%1,%2,%3}, [%4];"
        : "=r"(r[0]), "=r"(r[1]), "=r"(r[2]), "=r"(r[3]) : "r"(addr));
}
__device__ __forceinline__ void mma16816(float (&d)[4], const uint32_t (&a)[4],
                                         uint32_t b0, uint32_t b1) {
    asm volatile("mma.sync.aligned.m16n8k16.row.col.f32.bf16.bf16.f32 "
        "{%0,%1,%2,%3}, {%4,%5,%6,%7}, {%8,%9}, {%0,%1,%2,%3};"
        : "+f"(d[0]), "+f"(d[1]), "+f"(d[2]), "+f"(d[3])
        : "r"(a[0]), "r"(a[1]), "r"(a[2]), "r"(a[3]), "r"(b0), "r"(b1));
}

// ---------------------------------------------------------------------------
// Packed f32x2 helpers (attention kernels)
// ---------------------------------------------------------------------------
typedef unsigned long long u64;
__device__ __forceinline__ u64 bcast2(float v) {
    u64 r; asm("mov.b64 %0, {%1, %1};" : "=l"(r) : "f"(v)); return r;
}
__device__ __forceinline__ u64 ffma2(u64 a, u64 b, u64 c) {
    u64 d; asm("fma.rn.f32x2 %0, %1, %2, %3;" : "=l"(d) : "l"(a), "l"(b), "l"(c)); return d;
}
__device__ __forceinline__ float2 unpack2(u64 v) {
    float2 f; asm("mov.b64 {%0, %1}, %2;" : "=f"(f.x), "=f"(f.y) : "l"(v)); return f;
}

// ---------------------------------------------------------------------------
// Weight prep: OIHW fp32 -> bf16 hi/lo tiles [64co][64ci], 128B rows swizzled
// ---------------------------------------------------------------------------
__global__ void prep_w_k(const float* __restrict__ Wq,
                         const float* __restrict__ Wk,
                         const float* __restrict__ Wv)
{
    int i = blockIdx.x*blockDim.x + threadIdx.x;
    if (i >= 3*3*3*64*64) return;
    int ci = i & 63; int t = i >> 6;
    int co = t & 63; t >>= 6;
    int kx = t % 3;  t /= 3;
    int ky = t % 3;  t /= 3;
    int sel = t;
    const float* Ws = (sel == 0) ? Wq : ((sel == 1) ? Wk : Wv);
    float v = Ws[((co*Cn + ci)*3 + ky)*3 + kx];
    __nv_bfloat16 hi = __float2bfloat16(v);
    __nv_bfloat16 lo = __float2bfloat16(v - __bfloat162float(hi));
    size_t tbase = (size_t)(((sel*3 + ky)*3 + kx)*2)*8192;
    uint32_t off = (uint32_t)co*128 + (((uint32_t)ci*2) ^ (((uint32_t)co & 7) << 4));
    *(__nv_bfloat16*)(g_wb16 + tbase + off)        = hi;
    *(__nv_bfloat16*)(g_wb16 + tbase + 8192 + off) = lo;
}

// ---------------------------------------------------------------------------
// Fused 3x3 conv via mma.sync bf16 (hi/lo split, 3 combos).
// Grid (16 htiles, 8 b, 6 = sel*2 + co-half). Block 256 = 8 warps,
// each warp owns M=16 (w), CTA covers M=128 x N=32.
// SMEM: W 18 tiles x 4KB = 72KB; A ring 3 slots x 2 splits x [130][128B] = 97.5KB
// ---------------------------------------------------------------------------
#define CONV_SMEM (73728 + 99840 + 128)

__global__ __launch_bounds__(256) void conv_mma_k(const float* __restrict__ x,
                                                  const float* __restrict__ bq,
                                                  const float* __restrict__ bk,
                                                  const float* __restrict__ bv)
{
    extern __shared__ char sm[];
    char* SW = sm;                     // 18 x 4096
    char* SA = sm + 73728;             // 6 x 16640
    float* sbias = (float*)(sm + 73728 + 99840);
    const int tid = threadIdx.x, lane = tid & 31, wid = tid >> 5;
    const int b = blockIdx.y;
    const int sel = blockIdx.z >> 1, co0 = (blockIdx.z & 1) * 32;
    const int h0 = blockIdx.x * 8;
    const float* bias = (sel == 0) ? bq : ((sel == 1) ? bk : bv);
    float* gout = (sel == 0) ? g_q : ((sel == 1) ? g_k : g_v);

    // Stage weight tiles (rows co0..co0+31 of each of 18 tiles)
    {
        const char* gw = g_wb16 + (size_t)sel*9*2*8192 + (size_t)co0*128;
        for (int i = tid; i < 18*256; i += 256) {
            int t = i >> 8, seg = i & 255;
            *(uint4*)(SW + t*4096 + seg*16) =
                *(const uint4*)(gw + (size_t)t*8192 + seg*16);
        }
    }
    if (tid < 32) sbias[tid] = bias[co0 + tid];
    // Zero boundary rows (w=-1 and w=128) of all 6 slot-split tiles
    if (tid < 96) {
        int s6 = tid / 16, k = tid % 16;
        uint32_t off = s6*16640 + ((k < 8) ? 0u : 16512u) + (k & 7)*16;
        *(uint4*)(SA + off) = make_uint4(0,0,0,0);
    }

    const uint32_t SAb = smem_u32(SA);
    const uint32_t SWb = smem_u32(SW);
    const int m0 = wid * 16;

    // lane-constant fragment address pieces
    const int aRowSel = lane & 15;
    const int aColSel = (lane & 16) ? 16 : 0;
    const int bRowSel = (lane & 7) + ((lane & 16) ? 8 : 0);
    const int bColSel = (lane & 8) ? 16 : 0;

    for (int hh = 0; hh < 8; hh++) {
        const int h = h0 + hh;
        if (hh) __syncthreads();     // prior compute done before ring overwrite

        // stage needed x rows (ring slot = (row+3)%3), hi/lo bf16, swizzled
        for (int rr = (hh == 0 ? -1 : 1); rr <= 1; rr++) {
            const int r = h + rr;
            const int s = (r + 3) % 3;
            char* hi = SA + (size_t)(s*2 + 0)*16640;
            char* lo = SA + (size_t)(s*2 + 1)*16640;
            const bool valid = ((unsigned)r < 128u);
            const float* xr = x + ((size_t)b*64*128 + (size_t)(valid ? r : 0))*128;
            for (int id = tid; id < 4096; id += 256) {
                int w = id & 127, cp = id >> 7;
                float v0 = 0.f, v1 = 0.f;
                if (valid) {
                    v0 = xr[(size_t)(cp*2)    *16384 + w];
                    v1 = xr[(size_t)(cp*2 + 1)*16384 + w];
                }
                __nv_bfloat16 h0b = __float2bfloat16(v0);
                __nv_bfloat16 l0b = __float2bfloat16(v0 - __bfloat162float(h0b));
                __nv_bfloat16 h1b = __float2bfloat16(v1);
                __nv_bfloat16 l1b = __float2bfloat16(v1 - __bfloat162float(h1b));
                uint32_t row = (uint32_t)w + 1;
                uint32_t off = row*128 + (((uint32_t)cp*4) ^ ((row & 7) << 4));
                *(uint32_t*)(hi + off) =
                    ((uint32_t)__bfloat16_as_ushort(h1b) << 16) | __bfloat16_as_ushort(h0b);
                *(uint32_t*)(lo + off) =
                    ((uint32_t)__bfloat16_as_ushort(l1b) << 16) | __bfloat16_as_ushort(l0b);
            }
        }
        __syncthreads();

        float acc[4][4];
#pragma unroll
        for (int i = 0; i < 4; i++)
#pragma unroll
            for (int j = 0; j < 4; j++) acc[i][j] = 0.f;

#pragma unroll
        for (int ky = 0; ky < 3; ky++) {
            const int r = h + ky - 1;
            const int s = (r + 3) % 3;
            const uint32_t Ahi = SAb + (uint32_t)(s*2)*16640;
            const uint32_t Alo = Ahi + 16640;
#pragma unroll
            for (int kx = 0; kx < 3; kx++) {
                const int arow = m0 + kx + aRowSel;
                const uint32_t aoff = (uint32_t)arow*128;
                const uint32_t axor = ((uint32_t)arow & 7) << 4;
                const uint32_t Wt = SWb + (uint32_t)((ky*3 + kx)*2)*4096;
                const uint32_t brow0 = (uint32_t)bRowSel;
                const uint32_t brow1 = (uint32_t)bRowSel + 16;
                const uint32_t boff0 = brow0*128, bx0 = (brow0 & 7) << 4;
                const uint32_t boff1 = brow1*128, bx1 = (brow1 & 7) << 4;
#pragma unroll
                for (int cc = 0; cc < 4; cc++) {
                    uint32_t ah[4], al[4], bh[8], bl[8];
                    const uint32_t acol = ((uint32_t)(cc*32 + aColSel)) ^ axor;
                    ldsm4(ah, Ahi + aoff + acol);
                    ldsm4(al, Alo + aoff + acol);
                    const uint32_t bc0 = ((uint32_t)(cc*32 + bColSel)) ^ bx0;
                    const uint32_t bc1 = ((uint32_t)(cc*32 + bColSel)) ^ bx1;
                    ldsm4(bh + 0, Wt + boff0 + bc0);
                    ldsm4(bh + 4, Wt + boff1 + bc1);
                    ldsm4(bl + 0, Wt + 4096 + boff0 + bc0);
                    ldsm4(bl + 4, Wt + 4096 + boff1 + bc1);
#pragma unroll
                    for (int nt = 0; nt < 4; nt++) {
                        mma16816(acc[nt], ah, bh[nt*2], bh[nt*2 + 1]);
                        mma16816(acc[nt], al, bh[nt*2], bh[nt*2 + 1]);
                        mma16816(acc[nt], ah, bl[nt*2], bl[nt*2 + 1]);
                    }
                }
            }
        }

        // epilogue: fragment -> g[sel][b][h][w][c] + bias
        const int wr = m0 + (lane >> 2);
        const int cb = (lane & 3) * 2;
        float* op = gout + ((size_t)(b*Hn + h)*Wn)*Cn;
#pragma unroll
        for (int nt = 0; nt < 4; nt++) {
            const int c = co0 + nt*8 + cb;
            const float b0 = sbias[nt*8 + cb], b1 = sbias[nt*8 + cb + 1];
            *(float2*)&op[(size_t)wr*Cn + c] =
                make_float2(acc[nt][0] + b0, acc[nt][1] + b1);
            *(float2*)&op[(size_t)(wr + 8)*Cn + c] =
                make_float2(acc[nt][2] + b0, acc[nt][3] + b1);
        }
    }
}

// ---------------------------------------------------------------------------
// eH logits: block (w,b). C[h][g] = sum_c q[b,h,w,c]*k[b,g,w,c]; diag -> -inf
// ---------------------------------------------------------------------------
__global__ __launch_bounds__(256) void eh_logits_k()
{
    __shared__ float qs[Hn][17];
    __shared__ float kst[16][132];
    const int w = blockIdx.x, b = blockIdx.y;
    const int tx = threadIdx.x & 15, ty = threadIdx.x >> 4;
    const int g0 = tx*8, h0 = ty*8;
    u64 acc[8][4];
#pragma unroll
    for (int j = 0; j < 8; j++)
#pragma unroll
        for (int l = 0; l < 4; l++) acc[j][l] = 0ull;
    const float* qb = g_q + ((size_t)b*Hn*Wn + w)*Cn;
    const float* kb = g_k + ((size_t)b*Hn*Wn + w)*Cn;

    for (int cc = 0; cc < Cn; cc += 16) {
        __syncthreads();
        for (int i = threadIdx.x; i < Hn*16; i += 256) {
            int r = i >> 4, cl = i & 15;
            qs[r][cl]  = qb[(size_t)r*Wn*Cn + cc + cl];
            kst[cl][r] = kb[(size_t)r*Wn*Cn + cc + cl];
        }
        __syncthreads();
#pragma unroll
        for (int kk = 0; kk < 16; kk++) {
            u64 aa[8];
#pragma unroll
            for (int j = 0; j < 8; j++) aa[j] = bcast2(qs[h0+j][kk]);
            const ulonglong2 b01 = *(const ulonglong2*)&kst[kk][g0];
            const ulonglong2 b23 = *(const ulonglong2*)&kst[kk][g0+4];
#pragma unroll
            for (int j = 0; j < 8; j++) {
                acc[j][0] = ffma2(aa[j], b01.x, acc[j][0]);
                acc[j][1] = ffma2(aa[j], b01.y, acc[j][1]);
                acc[j][2] = ffma2(aa[j], b23.x, acc[j][2]);
                acc[j][3] = ffma2(aa[j], b23.y, acc[j][3]);
            }
        }
    }

#pragma unroll
    for (int j = 0; j < 8; j++) {
        int h = h0 + j;
        float* row = g_att + ((size_t)(b*Hn + h)*Wn + w)*256 + g0;
        float2 p0 = unpack2(acc[j][0]), p1 = unpack2(acc[j][1]);
        float2 p2 = unpack2(acc[j][2]), p3 = unpack2(acc[j][3]);
        float4 r0, r1;
        r0.x = (h == g0  ) ? -CUDART_INF_F : p0.x;
        r0.y = (h == g0+1) ? -CUDART_INF_F : p0.y;
        r0.z = (h == g0+2) ? -CUDART_INF_F : p1.x;
        r0.w = (h == g0+3) ? -CUDART_INF_F : p1.y;
        r1.x = (h == g0+4) ? -CUDART_INF_F : p2.x;
        r1.y = (h == g0+5) ? -CUDART_INF_F : p2.y;
        r1.z = (h == g0+6) ? -CUDART_INF_F : p3.x;
        r1.w = (h == g0+7) ? -CUDART_INF_F : p3.y;
        *(float4*)&row[0] = r0;
        *(float4*)&row[4] = r1;
    }
}

// ---------------------------------------------------------------------------
// eW logits: block (h,b). C[w][g] = sum_c q[b,h,w,c]*k[b,h,g,c]
// ---------------------------------------------------------------------------
__global__ __launch_bounds__(256) void ew_logits_k()
{
    __shared__ float qs[Wn][17];
    __shared__ float kst[16][132];
    const int h = blockIdx.x, b = blockIdx.y;
    const int tx = threadIdx.x & 15, ty = threadIdx.x >> 4;
    const int g0 = tx*8, w0 = ty*8;
    u64 acc[8][4];
#pragma unroll
    for (int j = 0; j < 8; j++)
#pragma unroll
        for (int l = 0; l < 4; l++) acc[j][l] = 0ull;
    const float* qb = g_q + ((size_t)(b*Hn + h)*Wn)*Cn;
    const float* kb = g_k + ((size_t)(b*Hn + h)*Wn)*Cn;

    for (int cc = 0; cc < Cn; cc += 16) {
        __syncthreads();
        for (int i = threadIdx.x; i < Wn*16; i += 256) {
            int r = i >> 4, cl = i & 15;
            qs[r][cl]  = qb[r*Cn + cc + cl];
            kst[cl][r] = kb[r*Cn + cc + cl];
        }
        __syncthreads();
#pragma unroll
        for (int kk = 0; kk < 16; kk++) {
            u64 aa[8];
#pragma unroll
            for (int j = 0; j < 8; j++) aa[j] = bcast2(qs[w0+j][kk]);
            const ulonglong2 b01 = *(const ulonglong2*)&kst[kk][g0];
            const ulonglong2 b23 = *(const ulonglong2*)&kst[kk][g0+4];
#pragma unroll
            for (int j = 0; j < 8; j++) {
                acc[j][0] = ffma2(aa[j], b01.x, acc[j][0]);
                acc[j][1] = ffma2(aa[j], b01.y, acc[j][1]);
                acc[j][2] = ffma2(aa[j], b23.x, acc[j][2]);
                acc[j][3] = ffma2(aa[j], b23.y, acc[j][3]);
            }
        }
    }

#pragma unroll
    for (int j = 0; j < 8; j++) {
        float* row = g_att + ((size_t)(b*Hn + h)*Wn + (w0+j))*256 + 128 + g0;
        float2 p0 = unpack2(acc[j][0]), p1 = unpack2(acc[j][1]);
        float2 p2 = unpack2(acc[j][2]), p3 = unpack2(acc[j][3]);
        *(float4*)&row[0] = make_float4(p0.x, p0.y, p1.x, p1.y);
        *(float4*)&row[4] = make_float4(p2.x, p2.y, p3.x, p3.y);
    }
}

// ---------------------------------------------------------------------------
// Softmax over 256 logits per pixel (warp per pixel), in place.
// ---------------------------------------------------------------------------
__global__ __launch_bounds__(256) void softmax_k()
{
    int p = (blockIdx.x << 3) + (threadIdx.x >> 5);
    int lane = threadIdx.x & 31;
    float* row = g_att + (size_t)p*256;
    float4 v0 = *(float4*)&row[lane*8];
    float4 v1 = *(float4*)&row[lane*8 + 4];
    float m = fmaxf(fmaxf(fmaxf(v0.x,v0.y), fmaxf(v0.z,v0.w)),
                    fmaxf(fmaxf(v1.x,v1.y), fmaxf(v1.z,v1.w)));
#pragma unroll
    for (int o = 16; o; o >>= 1) m = fmaxf(m, __shfl_xor_sync(~0u, m, o));
    float e[8];
    e[0]=__expf(v0.x-m); e[1]=__expf(v0.y-m); e[2]=__expf(v0.z-m); e[3]=__expf(v0.w-m);
    e[4]=__expf(v1.x-m); e[5]=__expf(v1.y-m); e[6]=__expf(v1.z-m); e[7]=__expf(v1.w-m);
    float s = (e[0]+e[1])+(e[2]+e[3])+((e[4]+e[5])+(e[6]+e[7]));
#pragma unroll
    for (int o = 16; o; o >>= 1) s += __shfl_xor_sync(~0u, s, o);
    float r = 1.0f / s;
    *(float4*)&row[lane*8]     = make_float4(e[0]*r, e[1]*r, e[2]*r, e[3]*r);
    *(float4*)&row[lane*8 + 4] = make_float4(e[4]*r, e[5]*r, e[6]*r, e[7]*r);
}

// ---------------------------------------------------------------------------
// out_W: block (h,b). C[w][c] = sum_g attW[w][g] * v[b,h,g,c]
// ---------------------------------------------------------------------------
__global__ __launch_bounds__(256) void out_w_k()
{
    __shared__ float as[Wn][17];
    __shared__ float vs[16][68];
    const int h = blockIdx.x, b = blockIdx.y;
    const int tx = threadIdx.x & 15, ty = threadIdx.x >> 4;
    const int c0 = tx*4, w0 = ty*8;
    u64 acc[8][2];
#pragma unroll
    for (int j = 0; j < 8; j++) { acc[j][0] = 0ull; acc[j][1] = 0ull; }
    const float* ab = g_att + ((size_t)(b*Hn + h)*Wn)*256 + 128;
    const float* vb = g_v   + ((size_t)(b*Hn + h)*Wn)*Cn;

    for (int gc = 0; gc < Hn; gc += 16) {
        __syncthreads();
        for (int i = threadIdx.x; i < Wn*16; i += 256) {
            int r = i >> 4, kl = i & 15;
            as[r][kl] = ab[(size_t)r*256 + gc + kl];
        }
        for (int i = threadIdx.x; i < 16*Cn; i += 256) {
            int kl = i >> 6, c = i & 63;
            vs[kl][c] = vb[(gc + kl)*Cn + c];
        }
        __syncthreads();
#pragma unroll
        for (int kk = 0; kk < 16; kk++) {
            const ulonglong2 bv = *(const ulonglong2*)&vs[kk][c0];
#pragma unroll
            for (int j = 0; j < 8; j++) {
                u64 aa = bcast2(as[w0+j][kk]);
                acc[j][0] = ffma2(aa, bv.x, acc[j][0]);
                acc[j][1] = ffma2(aa, bv.y, acc[j][1]);
            }
        }
    }
    float* op = g_oW + ((size_t)(b*Hn + h)*Wn)*Cn;
#pragma unroll
    for (int j = 0; j < 8; j++) {
        float2 p0 = unpack2(acc[j][0]), p1 = unpack2(acc[j][1]);
        *(float4*)&op[(w0+j)*Cn + c0] = make_float4(p0.x, p0.y, p1.x, p1.y);
    }
}

// ---------------------------------------------------------------------------
// out_H: block (w,b). C[h][c] = sum_g attH[h][g] * v[b,g,w,c]
// ---------------------------------------------------------------------------
__global__ __launch_bounds__(256) void out_h_k()
{
    __shared__ float as[Hn][17];
    __shared__ float vs[16][68];
    const int w = blockIdx.x, b = blockIdx.y;
    const int tx = threadIdx.x & 15, ty = threadIdx.x >> 4;
    const int c0 = tx*4, h0 = ty*8;
    u64 acc[8][2];
#pragma unroll
    for (int j = 0; j < 8; j++) { acc[j][0] = 0ull; acc[j][1] = 0ull; }
    const float* ab = g_att + ((size_t)b*Hn*Wn + w)*256;
    const float* vb = g_v   + ((size_t)b*Hn*Wn + w)*Cn;

    for (int gc = 0; gc < Hn; gc += 16) {
        __syncthreads();
        for (int i = threadIdx.x; i < Hn*16; i += 256) {
            int r = i >> 4, kl = i & 15;
            as[r][kl] = ab[(size_t)r*Wn*256 + gc + kl];
        }
        for (int i = threadIdx.x; i < 16*Cn; i += 256) {
            int kl = i >> 6, c = i & 63;
            vs[kl][c] = vb[(size_t)(gc + kl)*Wn*Cn + c];
        }
        __syncthreads();
#pragma unroll
        for (int kk = 0; kk < 16; kk++) {
            const ulonglong2 bv = *(const ulonglong2*)&vs[kk][c0];
#pragma unroll
            for (int j = 0; j < 8; j++) {
                u64 aa = bcast2(as[h0+j][kk]);
                acc[j][0] = ffma2(aa, bv.x, acc[j][0]);
                acc[j][1] = ffma2(aa, bv.y, acc[j][1]);
            }
        }
    }
    float* op = g_oH + ((size_t)(b*Wn + w)*Hn)*Cn;
#pragma unroll
    for (int j = 0; j < 8; j++) {
        float2 p0 = unpack2(acc[j][0]), p1 = unpack2(acc[j][1]);
        *(float4*)&op[(h0+j)*Cn + c0] = make_float4(p0.x, p0.y, p1.x, p1.y);
    }
}

// ---------------------------------------------------------------------------
// Final: out[b][c][h][w] = gamma*(oH[b][w][h][c] + oW[b][h][w][c]) + x
// ---------------------------------------------------------------------------
__global__ __launch_bounds__(256) void final_k(const float* __restrict__ x,
                                               const float* __restrict__ gamma,
                                               float* __restrict__ out)
{
    __shared__ float s[Cn][33];
    const int w0 = blockIdx.x*32, h = blockIdx.y, b = blockIdx.z;
    const float g = gamma[0];
    for (int i = threadIdx.x; i < 32*Cn; i += 256) {
        int wl = i >> 6, c = i & 63;
        float a = g_oH[(((size_t)b*Wn + (w0+wl))*Hn + h)*Cn + c];
        float d = g_oW[(((size_t)b*Hn + h)*Wn + (w0+wl))*Cn + c];
        s[c][wl] = g*(a + d);
    }
    __syncthreads();
    for (int i = threadIdx.x; i < Cn*32; i += 256) {
        int c = i >> 5, wl = i & 31;
        size_t idx = (((size_t)b*Cn + c)*Hn + h)*Wn + w0 + wl;
        out[idx] = s[c][wl] + x[idx];
    }
}

// ---------------------------------------------------------------------------
extern "C" void kernel_launch(void* const* d_in, const int* in_sizes, int n_in,
                              void* d_out, int out_size)
{
    (void)in_sizes; (void)n_in; (void)out_size;
    const float* x     = (const float*)d_in[0];
    const float* Wq    = (const float*)d_in[1];
    const float* bq    = (const float*)d_in[2];
    const float* Wk    = (const float*)d_in[3];
    const float* bk    = (const float*)d_in[4];
    const float* Wv    = (const float*)d_in[5];
    const float* bv    = (const float*)d_in[6];
    const float* gamma = (const float*)d_in[7];
    float* out = (float*)d_out;

    static bool attr_set = false;
    if (!attr_set) {
        cudaFuncSetAttribute(conv_mma_k, cudaFuncAttributeMaxDynamicSharedMemorySize,
                             CONV_SMEM);
        attr_set = true;
    }

    prep_w_k<<<(3*3*3*64*64 + 255)/256, 256>>>(Wq, Wk, Wv);

    dim3 grid_conv(16, Bn, 6);   // (htile, b, sel*2 + co-half)
    conv_mma_k<<<grid_conv, 256, CONV_SMEM>>>(x, bq, bk, bv);

    dim3 grid_bh(Hn, Bn);
    dim3 grid_bw(Wn, Bn);
    eh_logits_k<<<grid_bw, 256>>>();
    ew_logits_k<<<grid_bh, 256>>>();

    softmax_k<<<(Bn*Hn*Wn)/8, 256>>>();

    out_h_k<<<grid_bw, 256>>>();
    out_w_k<<<grid_bh, 256>>>();

    dim3 grid_fin(Wn/32, Hn, Bn);
    final_k<<<grid_fin, 256>>>(x, gamma, out);
}

// round 7
// speedup vs baseline: 2.0122x; 1.2828x over previous
#include <cuda_runtime.h>
#include <cuda_bf16.h>
#include <math_constants.h>
#include <cstdint>

#define Bn 8
#define Cn 64
#define Hn 128
#define Wn 128

// ---------------------------------------------------------------------------
// Global scratch (no allocation allowed)
// ---------------------------------------------------------------------------
__device__ float g_q[Bn*Hn*Wn*Cn];          // [b][h][w][c]
__device__ float g_k[Bn*Hn*Wn*Cn];
__device__ float g_v[Bn*Hn*Wn*Cn];
__device__ float g_att[Bn*Hn*Wn*2*Hn];      // [b][h][w][256] raw logits
__device__ float g_oH[Bn*Hn*Wn*Cn];         // [b][w][h][c]
__device__ float g_oW[Bn*Hn*Wn*Cn];         // [b][h][w][c]
__device__ float2 g_msH[Bn*Hn*Wn];          // per-pixel (max, sumexp) of eH half
__device__ float2 g_msW[Bn*Hn*Wn];          // per-pixel (max, sumexp) of eW half
__device__ float2 g_ms[Bn*Hn*Wn];           // combined (max, 1/sum)
// bf16 hi/lo weight tiles, swizzled 128B rows:
// [sel][ky][kx][split] tiles of [64 co][64 ci], tile = 8192B
__device__ __align__(16) char g_wb16[3*3*3*2*8192];

// ---------------------------------------------------------------------------
// mma.sync / ldmatrix helpers (plain sm_80+ PTX — compiles for sm_103)
// ---------------------------------------------------------------------------
__device__ __forceinline__ uint32_t smem_u32(const void* p) {
    uint32_t a;
    asm("{ .reg .u64 t; cvta.to.shared.u64 t, %1; cvt.u32.u64 %0, t; }"
        : "=r"(a) : "l"(p));
    return a;
}
__device__ __forceinline__ void ldsm4(uint32_t* r, uint32_t addr) {
    asm volatile("ldmatrix.sync.aligned.m8n8.x4.shared.b16 {%0,%1,%2,%3}, [%4];"
        : "=r"(r[0]), "=r"(r[1]), "=r"(r[2]), "=r"(r[3]) : "r"(addr));
}
__device__ __forceinline__ void mma16816(float (&d)[4], const uint32_t (&a)[4],
                                         uint32_t b0, uint32_t b1) {
    asm volatile("mma.sync.aligned.m16n8k16.row.col.f32.bf16.bf16.f32 "
        "{%0,%1,%2,%3}, {%4,%5,%6,%7}, {%8,%9}, {%0,%1,%2,%3};"
        : "+f"(d[0]), "+f"(d[1]), "+f"(d[2]), "+f"(d[3])
        : "r"(a[0]), "r"(a[1]), "r"(a[2]), "r"(a[3]), "r"(b0), "r"(b1));
}

// ---------------------------------------------------------------------------
// Weight prep: OIHW fp32 -> bf16 hi/lo tiles [64co][64ci], 128B rows swizzled
// ---------------------------------------------------------------------------
__global__ void prep_w_k(const float* __restrict__ Wq,
                         const float* __restrict__ Wk,
                         const float* __restrict__ Wv)
{
    int i = blockIdx.x*blockDim.x + threadIdx.x;
    if (i >= 3*3*3*64*64) return;
    int ci = i & 63; int t = i >> 6;
    int co = t & 63; t >>= 6;
    int kx = t % 3;  t /= 3;
    int ky = t % 3;  t /= 3;
    int sel = t;
    const float* Ws = (sel == 0) ? Wq : ((sel == 1) ? Wk : Wv);
    float v = Ws[((co*Cn + ci)*3 + ky)*3 + kx];
    __nv_bfloat16 hi = __float2bfloat16(v);
    __nv_bfloat16 lo = __float2bfloat16(v - __bfloat162float(hi));
    size_t tbase = (size_t)(((sel*3 + ky)*3 + kx)*2)*8192;
    uint32_t off = (uint32_t)co*128 + (((uint32_t)ci*2) ^ (((uint32_t)co & 7) << 4));
    *(__nv_bfloat16*)(g_wb16 + tbase + off)        = hi;
    *(__nv_bfloat16*)(g_wb16 + tbase + 8192 + off) = lo;
}

// ---------------------------------------------------------------------------
// Fused 3x3 conv via mma.sync bf16 (hi/lo split, 3 combos).  (unchanged R4)
// ---------------------------------------------------------------------------
#define CONV_SMEM (73728 + 99840 + 128)

__global__ __launch_bounds__(256) void conv_mma_k(const float* __restrict__ x,
                                                  const float* __restrict__ bq,
                                                  const float* __restrict__ bk,
                                                  const float* __restrict__ bv)
{
    extern __shared__ char sm[];
    char* SW = sm;                     // 18 x 4096
    char* SA = sm + 73728;             // 6 x 16640
    float* sbias = (float*)(sm + 73728 + 99840);
    const int tid = threadIdx.x, lane = tid & 31, wid = tid >> 5;
    const int b = blockIdx.y;
    const int sel = blockIdx.z >> 1, co0 = (blockIdx.z & 1) * 32;
    const int h0 = blockIdx.x * 8;
    const float* bias = (sel == 0) ? bq : ((sel == 1) ? bk : bv);
    float* gout = (sel == 0) ? g_q : ((sel == 1) ? g_k : g_v);

    {
        const char* gw = g_wb16 + (size_t)sel*9*2*8192 + (size_t)co0*128;
        for (int i = tid; i < 18*256; i += 256) {
            int t = i >> 8, seg = i & 255;
            *(uint4*)(SW + t*4096 + seg*16) =
                *(const uint4*)(gw + (size_t)t*8192 + seg*16);
        }
    }
    if (tid < 32) sbias[tid] = bias[co0 + tid];
    if (tid < 96) {
        int s6 = tid / 16, k = tid % 16;
        uint32_t off = s6*16640 + ((k < 8) ? 0u : 16512u) + (k & 7)*16;
        *(uint4*)(SA + off) = make_uint4(0,0,0,0);
    }

    const uint32_t SAb = smem_u32(SA);
    const uint32_t SWb = smem_u32(SW);
    const int m0 = wid * 16;

    const int aRowSel = lane & 15;
    const int aColSel = (lane & 16) ? 16 : 0;
    const int bRowSel = (lane & 7) + ((lane & 16) ? 8 : 0);
    const int bColSel = (lane & 8) ? 16 : 0;

    for (int hh = 0; hh < 8; hh++) {
        const int h = h0 + hh;
        if (hh) __syncthreads();

        for (int rr = (hh == 0 ? -1 : 1); rr <= 1; rr++) {
            const int r = h + rr;
            const int s = (r + 3) % 3;
            char* hi = SA + (size_t)(s*2 + 0)*16640;
            char* lo = SA + (size_t)(s*2 + 1)*16640;
            const bool valid = ((unsigned)r < 128u);
            const float* xr = x + ((size_t)b*64*128 + (size_t)(valid ? r : 0))*128;
            for (int id = tid; id < 4096; id += 256) {
                int w = id & 127, cp = id >> 7;
                float v0 = 0.f, v1 = 0.f;
                if (valid) {
                    v0 = xr[(size_t)(cp*2)    *16384 + w];
                    v1 = xr[(size_t)(cp*2 + 1)*16384 + w];
                }
                __nv_bfloat16 h0b = __float2bfloat16(v0);
                __nv_bfloat16 l0b = __float2bfloat16(v0 - __bfloat162float(h0b));
                __nv_bfloat16 h1b = __float2bfloat16(v1);
                __nv_bfloat16 l1b = __float2bfloat16(v1 - __bfloat162float(h1b));
                uint32_t row = (uint32_t)w + 1;
                uint32_t off = row*128 + (((uint32_t)cp*4) ^ ((row & 7) << 4));
                *(uint32_t*)(hi + off) =
                    ((uint32_t)__bfloat16_as_ushort(h1b) << 16) | __bfloat16_as_ushort(h0b);
                *(uint32_t*)(lo + off) =
                    ((uint32_t)__bfloat16_as_ushort(l1b) << 16) | __bfloat16_as_ushort(l0b);
            }
        }
        __syncthreads();

        float acc[4][4];
#pragma unroll
        for (int i = 0; i < 4; i++)
#pragma unroll
            for (int j = 0; j < 4; j++) acc[i][j] = 0.f;

#pragma unroll
        for (int ky = 0; ky < 3; ky++) {
            const int r = h + ky - 1;
            const int s = (r + 3) % 3;
            const uint32_t Ahi = SAb + (uint32_t)(s*2)*16640;
            const uint32_t Alo = Ahi + 16640;
#pragma unroll
            for (int kx = 0; kx < 3; kx++) {
                const int arow = m0 + kx + aRowSel;
                const uint32_t aoff = (uint32_t)arow*128;
                const uint32_t axor = ((uint32_t)arow & 7) << 4;
                const uint32_t Wt = SWb + (uint32_t)((ky*3 + kx)*2)*4096;
                const uint32_t brow0 = (uint32_t)bRowSel;
                const uint32_t brow1 = (uint32_t)bRowSel + 16;
                const uint32_t boff0 = brow0*128, bx0 = (brow0 & 7) << 4;
                const uint32_t boff1 = brow1*128, bx1 = (brow1 & 7) << 4;
#pragma unroll
                for (int cc = 0; cc < 4; cc++) {
                    uint32_t ah[4], al[4], bh[8], bl[8];
                    const uint32_t acol = ((uint32_t)(cc*32 + aColSel)) ^ axor;
                    ldsm4(ah, Ahi + aoff + acol);
                    ldsm4(al, Alo + aoff + acol);
                    const uint32_t bc0 = ((uint32_t)(cc*32 + bColSel)) ^ bx0;
                    const uint32_t bc1 = ((uint32_t)(cc*32 + bColSel)) ^ bx1;
                    ldsm4(bh + 0, Wt + boff0 + bc0);
                    ldsm4(bh + 4, Wt + boff1 + bc1);
                    ldsm4(bl + 0, Wt + 4096 + boff0 + bc0);
                    ldsm4(bl + 4, Wt + 4096 + boff1 + bc1);
#pragma unroll
                    for (int nt = 0; nt < 4; nt++) {
                        mma16816(acc[nt], ah, bh[nt*2], bh[nt*2 + 1]);
                        mma16816(acc[nt], al, bh[nt*2], bh[nt*2 + 1]);
                        mma16816(acc[nt], ah, bl[nt*2], bl[nt*2 + 1]);
                    }
                }
            }
        }

        const int wr = m0 + (lane >> 2);
        const int cb = (lane & 3) * 2;
        float* op = gout + ((size_t)(b*Hn + h)*Wn)*Cn;
#pragma unroll
        for (int nt = 0; nt < 4; nt++) {
            const int c = co0 + nt*8 + cb;
            const float b0 = sbias[nt*8 + cb], b1 = sbias[nt*8 + cb + 1];
            *(float2*)&op[(size_t)wr*Cn + c] =
                make_float2(acc[nt][0] + b0, acc[nt][1] + b1);
            *(float2*)&op[(size_t)(wr + 8)*Cn + c] =
                make_float2(acc[nt][2] + b0, acc[nt][3] + b1);
        }
    }
}

// ---------------------------------------------------------------------------
// Logits via mma.sync (mode 0 = eH per (w,b), mode 1 = eW per (h,b)).
// C[row][g] = sum_c q[row,c]*k[g,c]. Writes raw logits to g_att and per-row
// (max, sumexp) partials to g_msH / g_msW.
// ---------------------------------------------------------------------------
#define LOGITS_SMEM (4*16384)

__global__ __launch_bounds__(256) void logits_mma_k(int mode)
{
    extern __shared__ char sm[];
    char* QH = sm;            char* QL = sm + 16384;
    char* KH = sm + 32768;    char* KL = sm + 49152;
    const int tid = threadIdx.x, lane = tid & 31, wid = tid >> 5;
    const int p = blockIdx.x, b = blockIdx.y;

    const size_t qkBase = mode ? ((size_t)(b*Hn + p)*Wn)*Cn
                               : ((size_t)b*Hn*Wn + p)*Cn;
    const int rowStr = mode ? Cn : Wn*Cn;

    for (int i = tid; i < 8192; i += 256) {
        int tsel = i >> 12, rem = i & 4095;
        int r = rem >> 5, cp = rem & 31;
        const float* src = (tsel ? g_k : g_q) + qkBase + (size_t)r*rowStr + cp*2;
        float2 v = *(const float2*)src;
        __nv_bfloat16 h0 = __float2bfloat16(v.x);
        __nv_bfloat16 l0 = __float2bfloat16(v.x - __bfloat162float(h0));
        __nv_bfloat16 h1 = __float2bfloat16(v.y);
        __nv_bfloat16 l1 = __float2bfloat16(v.y - __bfloat162float(h1));
        uint32_t off = (uint32_t)r*128 + (((uint32_t)cp*4) ^ (((uint32_t)r & 7) << 4));
        *(uint32_t*)((tsel ? KH : QH) + off) =
            ((uint32_t)__bfloat16_as_ushort(h1) << 16) | __bfloat16_as_ushort(h0);
        *(uint32_t*)((tsel ? KL : QL) + off) =
            ((uint32_t)__bfloat16_as_ushort(l1) << 16) | __bfloat16_as_ushort(l0);
    }
    __syncthreads();

    const uint32_t QHb = smem_u32(QH), QLb = smem_u32(QL);
    const uint32_t KHb = smem_u32(KH), KLb = smem_u32(KL);
    const int m0 = wid * 16;
    const int aRowSel = lane & 15;
    const int aColSel = (lane & 16) ? 16 : 0;
    const int bRowSel = (lane & 7) + ((lane & 16) ? 8 : 0);
    const int bColSel = (lane & 8) ? 16 : 0;

    float acc[16][4];
#pragma unroll
    for (int i = 0; i < 16; i++)
#pragma unroll
        for (int j = 0; j < 4; j++) acc[i][j] = 0.f;

#pragma unroll
    for (int kc = 0; kc < 4; kc++) {
        uint32_t ah[4], al[4];
        const int arow = m0 + aRowSel;
        const uint32_t aoff = (uint32_t)arow*128 +
            (((uint32_t)(kc*32 + aColSel)) ^ (((uint32_t)arow & 7) << 4));
        ldsm4(ah, QHb + aoff);
        ldsm4(al, QLb + aoff);
#pragma unroll
        for (int half = 0; half < 2; half++) {
            uint32_t bh[16], bl[16];
#pragma unroll
            for (int t = 0; t < 4; t++) {
                const int brow = bRowSel + 16*(half*4 + t);
                const uint32_t boff = (uint32_t)brow*128 +
                    (((uint32_t)(kc*32 + bColSel)) ^ (((uint32_t)brow & 7) << 4));
                ldsm4(bh + 4*t, KHb + boff);
                ldsm4(bl + 4*t, KLb + boff);
            }
#pragma unroll
            for (int nt = 0; nt < 8; nt++) {
                const int a = half*8 + nt;
                mma16816(acc[a], ah, bh[nt*2], bh[nt*2 + 1]);
                mma16816(acc[a], al, bh[nt*2], bh[nt*2 + 1]);
                mma16816(acc[a], ah, bl[nt*2], bl[nt*2 + 1]);
            }
        }
    }

    // Epilogue: mask (eH), store logits, per-row (max, sumexp) partials
    const size_t attBase = mode ? (((size_t)(b*Hn + p)*Wn)*256 + 128)
                                : (((size_t)b*Hn*Wn + p)*256);
    const size_t attRowStr = mode ? 256 : (size_t)Wn*256;
    const int msBase = mode ? (b*Hn + p)*Wn : b*Hn*Wn + p;
    const int msStr  = mode ? 1 : Wn;
    float2* msOut = mode ? g_msW : g_msH;

#pragma unroll
    for (int half2 = 0; half2 < 2; half2++) {
        const int row = m0 + (lane >> 2) + half2*8;
        float vals[32];
#pragma unroll
        for (int nt = 0; nt < 16; nt++) {
            const int g = nt*8 + (lane & 3)*2;
            float v0 = acc[nt][half2*2 + 0];
            float v1 = acc[nt][half2*2 + 1];
            if (!mode && row == g)     v0 = -CUDART_INF_F;
            if (!mode && row == g + 1) v1 = -CUDART_INF_F;
            *(float2*)&g_att[attBase + (size_t)row*attRowStr + g] = make_float2(v0, v1);
            vals[nt*2] = v0; vals[nt*2 + 1] = v1;
        }
        float m = vals[0];
#pragma unroll
        for (int i = 1; i < 32; i++) m = fmaxf(m, vals[i]);
        m = fmaxf(m, __shfl_xor_sync(~0u, m, 1));
        m = fmaxf(m, __shfl_xor_sync(~0u, m, 2));
        float s = 0.f;
#pragma unroll
        for (int i = 0; i < 32; i++) s += __expf(vals[i] - m);
        s += __shfl_xor_sync(~0u, s, 1);
        s += __shfl_xor_sync(~0u, s, 2);
        if ((lane & 3) == 0) msOut[msBase + row*msStr] = make_float2(m, s);
    }
}

// ---------------------------------------------------------------------------
// Combine the two per-row (max, sumexp) halves -> (max, 1/sum) per pixel
// ---------------------------------------------------------------------------
__global__ __launch_bounds__(256) void combine_ms_k()
{
    int i = blockIdx.x*256 + threadIdx.x;
    float2 a = g_msH[i], c = g_msW[i];
    float m = fmaxf(a.x, c.x);
    float s = a.y*__expf(a.x - m) + c.y*__expf(c.x - m);
    g_ms[i] = make_float2(m, 1.0f / s);
}

// ---------------------------------------------------------------------------
// Output GEMMs via mma.sync (mode 0 = out_W per (h,b), mode 1 = out_H per (w,b))
// C[row][c] = sum_g prob[row][g] * v[g][c].  B operand staged TRANSPOSED:
// VT[c][g] tiles so that B = [N=c rows][K=g cols] row-major (mma row.col).
// ---------------------------------------------------------------------------
#define OUT_SMEM (6*16384)

__global__ __launch_bounds__(256) void out_mma_k(int mode)
{
    extern __shared__ char sm[];
    char* AH0 = sm;            char* AH1 = sm + 16384;
    char* AL0 = sm + 32768;    char* AL1 = sm + 49152;
    char* VTH0 = sm + 65536;   char* VTH1 = sm + 73728;
    char* VTL0 = sm + 81920;   char* VTL1 = sm + 90112;
    const int tid = threadIdx.x, lane = tid & 31, wid = tid >> 5;
    const int p = blockIdx.x, b = blockIdx.y;

    const size_t aBase = mode ? (((size_t)b*Hn*Wn + p)*256)
                              : (((size_t)(b*Hn + p)*Wn)*256 + 128);
    const size_t aRowStr = mode ? (size_t)Wn*256 : 256;
    const int msBase = mode ? b*Hn*Wn + p : (b*Hn + p)*Wn;
    const int msStr  = mode ? Wn : 1;
    const float* vB = g_v + (mode ? ((size_t)b*Hn*Wn + p)*Cn
                                  : ((size_t)(b*Hn + p)*Wn)*Cn);
    const int vStr = mode ? Wn*Cn : Cn;
    float* oB = (mode ? g_oH : g_oW) + ((size_t)(b*Hn + p)*Wn)*Cn;

    // Stage A: probabilities hi/lo (two 64-g tiles, [row][g] layout)
    for (int i = tid; i < 8192; i += 256) {
        int r = i >> 6, gp = i & 63;
        float2 ms = g_ms[msBase + r*msStr];
        float2 l = *(const float2*)&g_att[aBase + (size_t)r*aRowStr + gp*2];
        float e0 = __expf(l.x - ms.x)*ms.y;
        float e1 = __expf(l.y - ms.x)*ms.y;
        __nv_bfloat16 h0 = __float2bfloat16(e0);
        __nv_bfloat16 l0 = __float2bfloat16(e0 - __bfloat162float(h0));
        __nv_bfloat16 h1 = __float2bfloat16(e1);
        __nv_bfloat16 l1 = __float2bfloat16(e1 - __bfloat162float(h1));
        int t = gp >> 5, cp = gp & 31;
        uint32_t off = (uint32_t)r*128 + (((uint32_t)cp*4) ^ (((uint32_t)r & 7) << 4));
        *(uint32_t*)((t ? AH1 : AH0) + off) =
            ((uint32_t)__bfloat16_as_ushort(h1) << 16) | __bfloat16_as_ushort(h0);
        *(uint32_t*)((t ? AL1 : AL0) + off) =
            ((uint32_t)__bfloat16_as_ushort(l1) << 16) | __bfloat16_as_ushort(l0);
    }
    // Stage V TRANSPOSED: VT[c][g] hi/lo, two 64-g tiles [64 c rows][64 g cols]
    for (int i = tid; i < 8192; i += 256) {
        int c = i & 63, g = i >> 6;
        float v = vB[(size_t)g*vStr + c];
        __nv_bfloat16 hb = __float2bfloat16(v);
        __nv_bfloat16 lb = __float2bfloat16(v - __bfloat162float(hb));
        int t = g >> 6, gin = g & 63;
        uint32_t off = (uint32_t)c*128 +
            (((uint32_t)gin*2) ^ (((uint32_t)c & 7) << 4));
        *(__nv_bfloat16*)((t ? VTH1 : VTH0) + off) = hb;
        *(__nv_bfloat16*)((t ? VTL1 : VTL0) + off) = lb;
    }
    __syncthreads();

    const uint32_t AH0b = smem_u32(AH0), AH1b = smem_u32(AH1);
    const uint32_t AL0b = smem_u32(AL0), AL1b = smem_u32(AL1);
    const uint32_t VTH0b = smem_u32(VTH0), VTH1b = smem_u32(VTH1);
    const uint32_t VTL0b = smem_u32(VTL0), VTL1b = smem_u32(VTL1);
    const int m0 = wid * 16;
    const int aRowSel = lane & 15;
    const int aColSel = (lane & 16) ? 16 : 0;
    const int bRowSel = (lane & 7) + ((lane & 16) ? 8 : 0);
    const int bColSel = (lane & 8) ? 16 : 0;

    float acc[8][4];
#pragma unroll
    for (int i = 0; i < 8; i++)
#pragma unroll
        for (int j = 0; j < 4; j++) acc[i][j] = 0.f;

#pragma unroll
    for (int kc = 0; kc < 8; kc++) {
        const uint32_t Ah = (kc < 4) ? AH0b : AH1b;
        const uint32_t Al = (kc < 4) ? AL0b : AL1b;
        const uint32_t Bh = (kc < 4) ? VTH0b : VTH1b;
        const uint32_t Bl = (kc < 4) ? VTL0b : VTL1b;
        const int cc = kc & 3;
        uint32_t ah[4], al[4];
        const int arow = m0 + aRowSel;
        const uint32_t aoff = (uint32_t)arow*128 +
            (((uint32_t)(cc*32 + aColSel)) ^ (((uint32_t)arow & 7) << 4));
        ldsm4(ah, Ah + aoff);
        ldsm4(al, Al + aoff);
        uint32_t bh[16], bl[16];
#pragma unroll
        for (int t = 0; t < 4; t++) {
            const int brow = bRowSel + 16*t;      // c rows 0..63 (N)
            const uint32_t boff = (uint32_t)brow*128 +
                (((uint32_t)(cc*32 + bColSel)) ^ (((uint32_t)brow & 7) << 4));
            ldsm4(bh + 4*t, Bh + boff);
            ldsm4(bl + 4*t, Bl + boff);
        }
#pragma unroll
        for (int nt = 0; nt < 8; nt++) {
            mma16816(acc[nt], ah, bh[nt*2], bh[nt*2 + 1]);
            mma16816(acc[nt], al, bh[nt*2], bh[nt*2 + 1]);
            mma16816(acc[nt], ah, bl[nt*2], bl[nt*2 + 1]);
        }
    }

#pragma unroll
    for (int half2 = 0; half2 < 2; half2++) {
        const int row = m0 + (lane >> 2) + half2*8;
#pragma unroll
        for (int nt = 0; nt < 8; nt++) {
            const int c = nt*8 + (lane & 3)*2;
            *(float2*)&oB[(size_t)row*Cn + c] =
                make_float2(acc[nt][half2*2 + 0], acc[nt][half2*2 + 1]);
        }
    }
}

// ---------------------------------------------------------------------------
// Final: out[b][c][h][w] = gamma*(oH[b][w][h][c] + oW[b][h][w][c]) + x
// ---------------------------------------------------------------------------
__global__ __launch_bounds__(256) void final_k(const float* __restrict__ x,
                                               const float* __restrict__ gamma,
                                               float* __restrict__ out)
{
    __shared__ float s[Cn][33];
    const int w0 = blockIdx.x*32, h = blockIdx.y, b = blockIdx.z;
    const float g = gamma[0];
    for (int i = threadIdx.x; i < 32*Cn; i += 256) {
        int wl = i >> 6, c = i & 63;
        float a = g_oH[(((size_t)b*Wn + (w0+wl))*Hn + h)*Cn + c];
        float d = g_oW[(((size_t)b*Hn + h)*Wn + (w0+wl))*Cn + c];
        s[c][wl] = g*(a + d);
    }
    __syncthreads();
    for (int i = threadIdx.x; i < Cn*32; i += 256) {
        int c = i >> 5, wl = i & 31;
        size_t idx = (((size_t)b*Cn + c)*Hn + h)*Wn + w0 + wl;
        out[idx] = s[c][wl] + x[idx];
    }
}

// ---------------------------------------------------------------------------
extern "C" void kernel_launch(void* const* d_in, const int* in_sizes, int n_in,
                              void* d_out, int out_size)
{
    (void)in_sizes; (void)n_in; (void)out_size;
    const float* x     = (const float*)d_in[0];
    const float* Wq    = (const float*)d_in[1];
    const float* bq    = (const float*)d_in[2];
    const float* Wk    = (const float*)d_in[3];
    const float* bk    = (const float*)d_in[4];
    const float* Wv    = (const float*)d_in[5];
    const float* bv    = (const float*)d_in[6];
    const float* gamma = (const float*)d_in[7];
    float* out = (float*)d_out;

    static bool attr_set = false;
    if (!attr_set) {
        cudaFuncSetAttribute(conv_mma_k, cudaFuncAttributeMaxDynamicSharedMemorySize,
                             CONV_SMEM);
        cudaFuncSetAttribute(logits_mma_k, cudaFuncAttributeMaxDynamicSharedMemorySize,
                             LOGITS_SMEM);
        cudaFuncSetAttribute(out_mma_k, cudaFuncAttributeMaxDynamicSharedMemorySize,
                             OUT_SMEM);
        attr_set = true;
    }

    prep_w_k<<<(3*3*3*64*64 + 255)/256, 256>>>(Wq, Wk, Wv);

    dim3 grid_conv(16, Bn, 6);   // (htile, b, sel*2 + co-half)
    conv_mma_k<<<grid_conv, 256, CONV_SMEM>>>(x, bq, bk, bv);

    dim3 grid_pb(128, Bn);
    logits_mma_k<<<grid_pb, 256, LOGITS_SMEM>>>(0);   // eH per (w,b)
    logits_mma_k<<<grid_pb, 256, LOGITS_SMEM>>>(1);   // eW per (h,b)

    combine_ms_k<<<(Bn*Hn*Wn)/256, 256>>>();

    out_mma_k<<<grid_pb, 256, OUT_SMEM>>>(0);         // out_W per (h,b)
    out_mma_k<<<grid_pb, 256, OUT_SMEM>>>(1);         // out_H per (w,b)

    dim3 grid_fin(Wn/32, Hn, Bn);
    final_k<<<grid_fin, 256>>>(x, gamma, out);
}

// round 8
// speedup vs baseline: 2.0962x; 1.0418x over previous
#include <cuda_runtime.h>
#include <cuda_bf16.h>
#include <math_constants.h>
#include <cstdint>

#define Bn 8
#define Cn 64
#define Hn 128
#define Wn 128

// ---------------------------------------------------------------------------
// Global scratch (no allocation allowed)
// ---------------------------------------------------------------------------
// q/k/v as packed bf16 hi/lo pairs over c: u32 = (c=2cp+1)<<16 | (c=2cp)
// index: ((b*Hn + h)*Wn + w)*32 + cp
__device__ uint32_t g_qh[Bn*Hn*Wn*32], g_ql[Bn*Hn*Wn*32];
__device__ uint32_t g_kh[Bn*Hn*Wn*32], g_kl[Bn*Hn*Wn*32];
__device__ uint32_t g_vh[Bn*Hn*Wn*32], g_vl[Bn*Hn*Wn*32];
// x pre-split: [b][h][cp][w] pairs over ci
__device__ uint32_t g_xh[Bn*Hn*32*Wn], g_xl[Bn*Hn*32*Wn];
// logits, consumer-friendly layouts
__device__ float g_attH[Bn*Wn*Hn*128];      // ((b*Wn + w)*Hn + h)*128 + g
__device__ float g_attW[Bn*Hn*Wn*128];      // ((b*Hn + h)*Wn + w)*128 + g
__device__ float g_oH[Bn*Hn*Wn*Cn];         // [b][w][h][c]
__device__ float g_oW[Bn*Hn*Wn*Cn];         // [b][h][w][c]
__device__ float2 g_msH[Bn*Hn*Wn];
__device__ float2 g_msW[Bn*Hn*Wn];
__device__ float2 g_ms[Bn*Hn*Wn];
// bf16 hi/lo weight tiles, swizzled 128B rows: [sel][ky][kx][split] 8KB each
__device__ __align__(16) char g_wb16[3*3*3*2*8192];

// ---------------------------------------------------------------------------
// helpers
// ---------------------------------------------------------------------------
__device__ __forceinline__ uint32_t smem_u32(const void* p) {
    uint32_t a;
    asm("{ .reg .u64 t; cvta.to.shared.u64 t, %1; cvt.u32.u64 %0, t; }"
        : "=r"(a) : "l"(p));
    return a;
}
__device__ __forceinline__ void ldsm4(uint32_t* r, uint32_t addr) {
    asm volatile("ldmatrix.sync.aligned.m8n8.x4.shared.b16 {%0,%1,%2,%3}, [%4];"
        : "=r"(r[0]), "=r"(r[1]), "=r"(r[2]), "=r"(r[3]) : "r"(addr));
}
__device__ __forceinline__ void mma16816(float (&d)[4], const uint32_t (&a)[4],
                                         uint32_t b0, uint32_t b1) {
    asm volatile("mma.sync.aligned.m16n8k16.row.col.f32.bf16.bf16.f32 "
        "{%0,%1,%2,%3}, {%4,%5,%6,%7}, {%8,%9}, {%0,%1,%2,%3};"
        : "+f"(d[0]), "+f"(d[1]), "+f"(d[2]), "+f"(d[3])
        : "r"(a[0]), "r"(a[1]), "r"(a[2]), "r"(a[3]), "r"(b0), "r"(b1));
}
// split a,b into hi bf16 pair + residual-lo bf16 pair
__device__ __forceinline__ void split_pack(float a, float b,
                                           uint32_t& hp, uint32_t& lp) {
    __nv_bfloat16 ha = __float2bfloat16(a);
    __nv_bfloat16 hb = __float2bfloat16(b);
    __nv_bfloat16 la = __float2bfloat16(a - __bfloat162float(ha));
    __nv_bfloat16 lb = __float2bfloat16(b - __bfloat162float(hb));
    hp = ((uint32_t)__bfloat16_as_ushort(hb) << 16) | __bfloat16_as_ushort(ha);
    lp = ((uint32_t)__bfloat16_as_ushort(lb) << 16) | __bfloat16_as_ushort(la);
}

// ---------------------------------------------------------------------------
// Weight prep (unchanged)
// ---------------------------------------------------------------------------
__global__ void prep_w_k(const float* __restrict__ Wq,
                         const float* __restrict__ Wk,
                         const float* __restrict__ Wv)
{
    int i = blockIdx.x*blockDim.x + threadIdx.x;
    if (i >= 3*3*3*64*64) return;
    int ci = i & 63; int t = i >> 6;
    int co = t & 63; t >>= 6;
    int kx = t % 3;  t /= 3;
    int ky = t % 3;  t /= 3;
    int sel = t;
    const float* Ws = (sel == 0) ? Wq : ((sel == 1) ? Wk : Wv);
    float v = Ws[((co*Cn + ci)*3 + ky)*3 + kx];
    __nv_bfloat16 hi = __float2bfloat16(v);
    __nv_bfloat16 lo = __float2bfloat16(v - __bfloat162float(hi));
    size_t tbase = (size_t)(((sel*3 + ky)*3 + kx)*2)*8192;
    uint32_t off = (uint32_t)co*128 + (((uint32_t)ci*2) ^ (((uint32_t)co & 7) << 4));
    *(__nv_bfloat16*)(g_wb16 + tbase + off)        = hi;
    *(__nv_bfloat16*)(g_wb16 + tbase + 8192 + off) = lo;
}

// ---------------------------------------------------------------------------
// x pre-split: NCHW fp32 -> [b][h][cp][w] packed bf16 hi/lo
// ---------------------------------------------------------------------------
__global__ __launch_bounds__(256) void prep_x_k(const float* __restrict__ x)
{
    int id = blockIdx.x*256 + threadIdx.x;        // total Bn*Hn*32*Wn
    int w = id & 127, cp = (id >> 7) & 31, h = (id >> 12) & 127, b = id >> 19;
    float v0 = x[(((size_t)(b*64 + cp*2    ))*128 + h)*128 + w];
    float v1 = x[(((size_t)(b*64 + cp*2 + 1))*128 + h)*128 + w];
    uint32_t hp, lp;
    split_pack(v0, v1, hp, lp);
    g_xh[id] = hp;
    g_xl[id] = lp;
}

// ---------------------------------------------------------------------------
// Fused 3x3 conv via mma.sync (index math unchanged from R4/R7).
// Staging now copies pre-split x; epilogue emits packed bf16 hi/lo q/k/v.
// ---------------------------------------------------------------------------
#define CONV_SMEM (73728 + 99840 + 128)

__global__ __launch_bounds__(256) void conv_mma_k(const float* __restrict__ bq,
                                                  const float* __restrict__ bk,
                                                  const float* __restrict__ bv)
{
    extern __shared__ char sm[];
    char* SW = sm;                     // 18 x 4096
    char* SA = sm + 73728;             // 6 x 16640
    float* sbias = (float*)(sm + 73728 + 99840);
    const int tid = threadIdx.x, lane = tid & 31, wid = tid >> 5;
    const int b = blockIdx.y;
    const int sel = blockIdx.z >> 1, co0 = (blockIdx.z & 1) * 32;
    const int h0 = blockIdx.x * 8;
    const float* bias = (sel == 0) ? bq : ((sel == 1) ? bk : bv);
    uint32_t* gh = (sel == 0) ? g_qh : ((sel == 1) ? g_kh : g_vh);
    uint32_t* gl = (sel == 0) ? g_ql : ((sel == 1) ? g_kl : g_vl);

    {
        const char* gw = g_wb16 + (size_t)sel*9*2*8192 + (size_t)co0*128;
        for (int i = tid; i < 18*256; i += 256) {
            int t = i >> 8, seg = i & 255;
            *(uint4*)(SW + t*4096 + seg*16) =
                *(const uint4*)(gw + (size_t)t*8192 + seg*16);
        }
    }
    if (tid < 32) sbias[tid] = bias[co0 + tid];
    if (tid < 96) {
        int s6 = tid / 16, k = tid % 16;
        uint32_t off = s6*16640 + ((k < 8) ? 0u : 16512u) + (k & 7)*16;
        *(uint4*)(SA + off) = make_uint4(0,0,0,0);
    }

    const uint32_t SAb = smem_u32(SA);
    const uint32_t SWb = smem_u32(SW);
    const int m0 = wid * 16;

    const int aRowSel = lane & 15;
    const int aColSel = (lane & 16) ? 16 : 0;
    const int bRowSel = (lane & 7) + ((lane & 16) ? 8 : 0);
    const int bColSel = (lane & 8) ? 16 : 0;

    for (int hh = 0; hh < 8; hh++) {
        const int h = h0 + hh;
        if (hh) __syncthreads();

        for (int rr = (hh == 0 ? -1 : 1); rr <= 1; rr++) {
            const int r = h + rr;
            const int s = (r + 3) % 3;
            char* hi = SA + (size_t)(s*2 + 0)*16640;
            char* lo = SA + (size_t)(s*2 + 1)*16640;
            const bool valid = ((unsigned)r < 128u);
            const uint32_t* xh = g_xh + (size_t)(b*Hn + (valid ? r : 0))*4096;
            const uint32_t* xl = g_xl + (size_t)(b*Hn + (valid ? r : 0))*4096;
            for (int id = tid; id < 4096; id += 256) {
                int w = id & 127, cp = id >> 7;
                uint32_t hv = 0, lv = 0;
                if (valid) {
                    hv = xh[cp*128 + w];
                    lv = xl[cp*128 + w];
                }
                uint32_t row = (uint32_t)w + 1;
                uint32_t off = row*128 + (((uint32_t)cp*4) ^ ((row & 7) << 4));
                *(uint32_t*)(hi + off) = hv;
                *(uint32_t*)(lo + off) = lv;
            }
        }
        __syncthreads();

        float acc[4][4];
#pragma unroll
        for (int i = 0; i < 4; i++)
#pragma unroll
            for (int j = 0; j < 4; j++) acc[i][j] = 0.f;

#pragma unroll
        for (int ky = 0; ky < 3; ky++) {
            const int r = h + ky - 1;
            const int s = (r + 3) % 3;
            const uint32_t Ahi = SAb + (uint32_t)(s*2)*16640;
            const uint32_t Alo = Ahi + 16640;
#pragma unroll
            for (int kx = 0; kx < 3; kx++) {
                const int arow = m0 + kx + aRowSel;
                const uint32_t aoff = (uint32_t)arow*128;
                const uint32_t axor = ((uint32_t)arow & 7) << 4;
                const uint32_t Wt = SWb + (uint32_t)((ky*3 + kx)*2)*4096;
                const uint32_t brow0 = (uint32_t)bRowSel;
                const uint32_t brow1 = (uint32_t)bRowSel + 16;
                const uint32_t boff0 = brow0*128, bx0 = (brow0 & 7) << 4;
                const uint32_t boff1 = brow1*128, bx1 = (brow1 & 7) << 4;
#pragma unroll
                for (int cc = 0; cc < 4; cc++) {
                    uint32_t ah[4], al[4], bh[8], bl[8];
                    const uint32_t acol = ((uint32_t)(cc*32 + aColSel)) ^ axor;
                    ldsm4(ah, Ahi + aoff + acol);
                    ldsm4(al, Alo + aoff + acol);
                    const uint32_t bc0 = ((uint32_t)(cc*32 + bColSel)) ^ bx0;
                    const uint32_t bc1 = ((uint32_t)(cc*32 + bColSel)) ^ bx1;
                    ldsm4(bh + 0, Wt + boff0 + bc0);
                    ldsm4(bh + 4, Wt + boff1 + bc1);
                    ldsm4(bl + 0, Wt + 4096 + boff0 + bc0);
                    ldsm4(bl + 4, Wt + 4096 + boff1 + bc1);
#pragma unroll
                    for (int nt = 0; nt < 4; nt++) {
                        mma16816(acc[nt], ah, bh[nt*2], bh[nt*2 + 1]);
                        mma16816(acc[nt], al, bh[nt*2], bh[nt*2 + 1]);
                        mma16816(acc[nt], ah, bl[nt*2], bl[nt*2 + 1]);
                    }
                }
            }
        }

        const int wr = m0 + (lane >> 2);
        const int cb = (lane & 3) * 2;
        const size_t rowBase = (size_t)(b*Hn + h)*Wn;
#pragma unroll
        for (int nt = 0; nt < 4; nt++) {
            const int c = co0 + nt*8 + cb;
            const float b0 = sbias[nt*8 + cb], b1 = sbias[nt*8 + cb + 1];
            uint32_t hp, lp;
            split_pack(acc[nt][0] + b0, acc[nt][1] + b1, hp, lp);
            gh[(rowBase + wr)*32 + (c >> 1)] = hp;
            gl[(rowBase + wr)*32 + (c >> 1)] = lp;
            split_pack(acc[nt][2] + b0, acc[nt][3] + b1, hp, lp);
            gh[(rowBase + wr + 8)*32 + (c >> 1)] = hp;
            gl[(rowBase + wr + 8)*32 + (c >> 1)] = lp;
        }
    }
}

// ---------------------------------------------------------------------------
// Logits via mma.sync (blockIdx.z: 0 = eH per (w,b), 1 = eW per (h,b)).
// Staging is a pure copy of pre-split q/k. Writes logits to g_attH / g_attW.
// ---------------------------------------------------------------------------
#define LOGITS_SMEM (4*16384)

__global__ __launch_bounds__(256) void logits_mma_k()
{
    extern __shared__ char sm[];
    char* QH = sm;            char* QL = sm + 16384;
    char* KH = sm + 32768;    char* KL = sm + 49152;
    const int tid = threadIdx.x, lane = tid & 31, wid = tid >> 5;
    const int p = blockIdx.x, b = blockIdx.y, mode = blockIdx.z;

    const size_t qkBase32 = mode ? (size_t)((b*Hn + p)*Wn)*32
                                 : (size_t)(b*Hn*Wn + p)*32;
    const int rowStr32 = mode ? 32 : Wn*32;

    for (int i = tid; i < 8192; i += 256) {
        int tsel = i >> 12, rem = i & 4095;
        int cp = rem & 31, r = rem >> 5;
        const uint32_t* sh = tsel ? g_kh : g_qh;
        const uint32_t* sl = tsel ? g_kl : g_ql;
        uint32_t hv = sh[qkBase32 + (size_t)r*rowStr32 + cp];
        uint32_t lv = sl[qkBase32 + (size_t)r*rowStr32 + cp];
        uint32_t off = (uint32_t)r*128 + (((uint32_t)cp*4) ^ (((uint32_t)r & 7) << 4));
        *(uint32_t*)((tsel ? KH : QH) + off) = hv;
        *(uint32_t*)((tsel ? KL : QL) + off) = lv;
    }
    __syncthreads();

    const uint32_t QHb = smem_u32(QH), QLb = smem_u32(QL);
    const uint32_t KHb = smem_u32(KH), KLb = smem_u32(KL);
    const int m0 = wid * 16;
    const int aRowSel = lane & 15;
    const int aColSel = (lane & 16) ? 16 : 0;
    const int bRowSel = (lane & 7) + ((lane & 16) ? 8 : 0);
    const int bColSel = (lane & 8) ? 16 : 0;

    float acc[16][4];
#pragma unroll
    for (int i = 0; i < 16; i++)
#pragma unroll
        for (int j = 0; j < 4; j++) acc[i][j] = 0.f;

#pragma unroll
    for (int kc = 0; kc < 4; kc++) {
        uint32_t ah[4], al[4];
        const int arow = m0 + aRowSel;
        const uint32_t aoff = (uint32_t)arow*128 +
            (((uint32_t)(kc*32 + aColSel)) ^ (((uint32_t)arow & 7) << 4));
        ldsm4(ah, QHb + aoff);
        ldsm4(al, QLb + aoff);
#pragma unroll
        for (int half = 0; half < 2; half++) {
            uint32_t bh[16], bl[16];
#pragma unroll
            for (int t = 0; t < 4; t++) {
                const int brow = bRowSel + 16*(half*4 + t);
                const uint32_t boff = (uint32_t)brow*128 +
                    (((uint32_t)(kc*32 + bColSel)) ^ (((uint32_t)brow & 7) << 4));
                ldsm4(bh + 4*t, KHb + boff);
                ldsm4(bl + 4*t, KLb + boff);
            }
#pragma unroll
            for (int nt = 0; nt < 8; nt++) {
                const int a = half*8 + nt;
                mma16816(acc[a], ah, bh[nt*2], bh[nt*2 + 1]);
                mma16816(acc[a], al, bh[nt*2], bh[nt*2 + 1]);
                mma16816(acc[a], ah, bl[nt*2], bl[nt*2 + 1]);
            }
        }
    }

    float* attOut = mode ? g_attW : g_attH;
    const size_t attBase = mode ? (size_t)((b*Hn + p)*Wn)*128
                                : (size_t)((b*Wn + p)*Hn)*128;
    const int msBase = mode ? (b*Hn + p)*Wn : b*Hn*Wn + p;
    const int msStr  = mode ? 1 : Wn;
    float2* msOut = mode ? g_msW : g_msH;

#pragma unroll
    for (int half2 = 0; half2 < 2; half2++) {
        const int row = m0 + (lane >> 2) + half2*8;
        float vals[32];
#pragma unroll
        for (int nt = 0; nt < 16; nt++) {
            const int g = nt*8 + (lane & 3)*2;
            float v0 = acc[nt][half2*2 + 0];
            float v1 = acc[nt][half2*2 + 1];
            if (!mode && row == g)     v0 = -CUDART_INF_F;
            if (!mode && row == g + 1) v1 = -CUDART_INF_F;
            *(float2*)&attOut[attBase + (size_t)row*128 + g] = make_float2(v0, v1);
            vals[nt*2] = v0; vals[nt*2 + 1] = v1;
        }
        float m = vals[0];
#pragma unroll
        for (int i = 1; i < 32; i++) m = fmaxf(m, vals[i]);
        m = fmaxf(m, __shfl_xor_sync(~0u, m, 1));
        m = fmaxf(m, __shfl_xor_sync(~0u, m, 2));
        float s = 0.f;
#pragma unroll
        for (int i = 0; i < 32; i++) s += __expf(vals[i] - m);
        s += __shfl_xor_sync(~0u, s, 1);
        s += __shfl_xor_sync(~0u, s, 2);
        if ((lane & 3) == 0) msOut[msBase + row*msStr] = make_float2(m, s);
    }
}

// ---------------------------------------------------------------------------
// Combine (max, sumexp) halves -> (max, 1/sum)
// ---------------------------------------------------------------------------
__global__ __launch_bounds__(256) void combine_ms_k()
{
    int i = blockIdx.x*256 + threadIdx.x;
    float2 a = g_msH[i], c = g_msW[i];
    float m = fmaxf(a.x, c.x);
    float s = a.y*__expf(a.x - m) + c.y*__expf(c.x - m);
    g_ms[i] = make_float2(m, 1.0f / s);
}

// ---------------------------------------------------------------------------
// Output GEMMs (blockIdx.z: 0 = out_W per (h,b), 1 = out_H per (w,b)).
// A = probabilities (exp on the fly), B = V transposed [c][g] hi/lo.
// ---------------------------------------------------------------------------
#define OUT_SMEM (6*16384)

__global__ __launch_bounds__(256) void out_mma_k()
{
    extern __shared__ char sm[];
    char* AH0 = sm;            char* AH1 = sm + 16384;
    char* AL0 = sm + 32768;    char* AL1 = sm + 49152;
    char* VTH0 = sm + 65536;   char* VTH1 = sm + 73728;
    char* VTL0 = sm + 81920;   char* VTL1 = sm + 90112;
    const int tid = threadIdx.x, lane = tid & 31, wid = tid >> 5;
    const int p = blockIdx.x, b = blockIdx.y, mode = blockIdx.z;

    const float* attSrc = mode ? g_attH : g_attW;
    const size_t aBase = mode ? (size_t)((b*Wn + p)*Hn)*128
                              : (size_t)((b*Hn + p)*Wn)*128;
    const int msBase = mode ? b*Hn*Wn + p : (b*Hn + p)*Wn;
    const int msStr  = mode ? Wn : 1;
    const size_t vBase32 = mode ? (size_t)(b*Hn*Wn + p)*32
                                : (size_t)((b*Hn + p)*Wn)*32;
    const int vStr32 = mode ? Wn*32 : 32;
    float* oB = (mode ? g_oH : g_oW) + ((size_t)(b*Hn + p)*Wn)*Cn;

    // Stage A: probabilities hi/lo
    for (int i = tid; i < 8192; i += 256) {
        int gp = i & 63, r = i >> 6;
        float2 ms = g_ms[msBase + r*msStr];
        float2 l = *(const float2*)&attSrc[aBase + (size_t)r*128 + gp*2];
        float e0 = __expf(l.x - ms.x)*ms.y;
        float e1 = __expf(l.y - ms.x)*ms.y;
        uint32_t hp, lp;
        split_pack(e0, e1, hp, lp);
        int t = gp >> 5, cp = gp & 31;
        uint32_t off = (uint32_t)r*128 + (((uint32_t)cp*4) ^ (((uint32_t)r & 7) << 4));
        *(uint32_t*)((t ? AH1 : AH0) + off) = hp;
        *(uint32_t*)((t ? AL1 : AL0) + off) = lp;
    }
    // Stage V transposed: VT[c][g] hi/lo (pure copy of pre-split v)
    for (int i = tid; i < 4096; i += 256) {
        int cp = i & 31, g = i >> 5;
        uint32_t hv = g_vh[vBase32 + (size_t)g*vStr32 + cp];
        uint32_t lv = g_vl[vBase32 + (size_t)g*vStr32 + cp];
        int t = g >> 6, gin = g & 63;
        int c0 = cp*2, c1 = cp*2 + 1;
        uint32_t off0 = (uint32_t)c0*128 + (((uint32_t)gin*2) ^ (((uint32_t)c0 & 7) << 4));
        uint32_t off1 = (uint32_t)c1*128 + (((uint32_t)gin*2) ^ (((uint32_t)c1 & 7) << 4));
        *(uint16_t*)((t ? VTH1 : VTH0) + off0) = (uint16_t)(hv & 0xFFFF);
        *(uint16_t*)((t ? VTH1 : VTH0) + off1) = (uint16_t)(hv >> 16);
        *(uint16_t*)((t ? VTL1 : VTL0) + off0) = (uint16_t)(lv & 0xFFFF);
        *(uint16_t*)((t ? VTL1 : VTL0) + off1) = (uint16_t)(lv >> 16);
    }
    __syncthreads();

    const uint32_t AH0b = smem_u32(AH0), AH1b = smem_u32(AH1);
    const uint32_t AL0b = smem_u32(AL0), AL1b = smem_u32(AL1);
    const uint32_t VTH0b = smem_u32(VTH0), VTH1b = smem_u32(VTH1);
    const uint32_t VTL0b = smem_u32(VTL0), VTL1b = smem_u32(VTL1);
    const int m0 = wid * 16;
    const int aRowSel = lane & 15;
    const int aColSel = (lane & 16) ? 16 : 0;
    const int bRowSel = (lane & 7) + ((lane & 16) ? 8 : 0);
    const int bColSel = (lane & 8) ? 16 : 0;

    float acc[8][4];
#pragma unroll
    for (int i = 0; i < 8; i++)
#pragma unroll
        for (int j = 0; j < 4; j++) acc[i][j] = 0.f;

#pragma unroll
    for (int kc = 0; kc < 8; kc++) {
        const uint32_t Ah = (kc < 4) ? AH0b : AH1b;
        const uint32_t Al = (kc < 4) ? AL0b : AL1b;
        const uint32_t Bh = (kc < 4) ? VTH0b : VTH1b;
        const uint32_t Bl = (kc < 4) ? VTL0b : VTL1b;
        const int cc = kc & 3;
        uint32_t ah[4], al[4];
        const int arow = m0 + aRowSel;
        const uint32_t aoff = (uint32_t)arow*128 +
            (((uint32_t)(cc*32 + aColSel)) ^ (((uint32_t)arow & 7) << 4));
        ldsm4(ah, Ah + aoff);
        ldsm4(al, Al + aoff);
        uint32_t bh[16], bl[16];
#pragma unroll
        for (int t = 0; t < 4; t++) {
            const int brow = bRowSel + 16*t;
            const uint32_t boff = (uint32_t)brow*128 +
                (((uint32_t)(cc*32 + bColSel)) ^ (((uint32_t)brow & 7) << 4));
            ldsm4(bh + 4*t, Bh + boff);
            ldsm4(bl + 4*t, Bl + boff);
        }
#pragma unroll
        for (int nt = 0; nt < 8; nt++) {
            mma16816(acc[nt], ah, bh[nt*2], bh[nt*2 + 1]);
            mma16816(acc[nt], al, bh[nt*2], bh[nt*2 + 1]);
            mma16816(acc[nt], ah, bl[nt*2], bl[nt*2 + 1]);
        }
    }

#pragma unroll
    for (int half2 = 0; half2 < 2; half2++) {
        const int row = m0 + (lane >> 2) + half2*8;
#pragma unroll
        for (int nt = 0; nt < 8; nt++) {
            const int c = nt*8 + (lane & 3)*2;
            *(float2*)&oB[(size_t)row*Cn + c] =
                make_float2(acc[nt][half2*2 + 0], acc[nt][half2*2 + 1]);
        }
    }
}

// ---------------------------------------------------------------------------
// Final: out[b][c][h][w] = gamma*(oH[b][w][h][c] + oW[b][h][w][c]) + x
// ---------------------------------------------------------------------------
__global__ __launch_bounds__(256) void final_k(const float* __restrict__ x,
                                               const float* __restrict__ gamma,
                                               float* __restrict__ out)
{
    __shared__ float s[Cn][33];
    const int w0 = blockIdx.x*32, h = blockIdx.y, b = blockIdx.z;
    const float g = gamma[0];
    for (int i = threadIdx.x; i < 32*Cn; i += 256) {
        int wl = i >> 6, c = i & 63;
        float a = g_oH[(((size_t)b*Wn + (w0+wl))*Hn + h)*Cn + c];
        float d = g_oW[(((size_t)b*Hn + h)*Wn + (w0+wl))*Cn + c];
        s[c][wl] = g*(a + d);
    }
    __syncthreads();
    for (int i = threadIdx.x; i < Cn*32; i += 256) {
        int c = i >> 5, wl = i & 31;
        size_t idx = (((size_t)b*Cn + c)*Hn + h)*Wn + w0 + wl;
        out[idx] = s[c][wl] + x[idx];
    }
}

// ---------------------------------------------------------------------------
extern "C" void kernel_launch(void* const* d_in, const int* in_sizes, int n_in,
                              void* d_out, int out_size)
{
    (void)in_sizes; (void)n_in; (void)out_size;
    const float* x     = (const float*)d_in[0];
    const float* Wq    = (const float*)d_in[1];
    const float* bq    = (const float*)d_in[2];
    const float* Wk    = (const float*)d_in[3];
    const float* bk    = (const float*)d_in[4];
    const float* Wv    = (const float*)d_in[5];
    const float* bv    = (const float*)d_in[6];
    const float* gamma = (const float*)d_in[7];
    float* out = (float*)d_out;

    static bool attr_set = false;
    if (!attr_set) {
        cudaFuncSetAttribute(conv_mma_k, cudaFuncAttributeMaxDynamicSharedMemorySize,
                             CONV_SMEM);
        cudaFuncSetAttribute(logits_mma_k, cudaFuncAttributeMaxDynamicSharedMemorySize,
                             LOGITS_SMEM);
        cudaFuncSetAttribute(out_mma_k, cudaFuncAttributeMaxDynamicSharedMemorySize,
                             OUT_SMEM);
        attr_set = true;
    }

    prep_w_k<<<(3*3*3*64*64 + 255)/256, 256>>>(Wq, Wk, Wv);
    prep_x_k<<<(Bn*Hn*32*Wn)/256, 256>>>(x);

    dim3 grid_conv(16, Bn, 6);   // (htile, b, sel*2 + co-half)
    conv_mma_k<<<grid_conv, 256, CONV_SMEM>>>(bq, bk, bv);

    dim3 grid_lg(128, Bn, 2);    // (p, b, mode)
    logits_mma_k<<<grid_lg, 256, LOGITS_SMEM>>>();

    combine_ms_k<<<(Bn*Hn*Wn)/256, 256>>>();

    out_mma_k<<<grid_lg, 256, OUT_SMEM>>>();

    dim3 grid_fin(Wn/32, Hn, Bn);
    final_k<<<grid_fin, 256>>>(x, gamma, out);
}

// round 10
// speedup vs baseline: 2.3386x; 1.1156x over previous
#include <cuda_runtime.h>
#include <cuda_bf16.h>
#include <math_constants.h>
#include <cstdint>

#define Bn 8
#define Cn 64
#define Hn 128
#define Wn 128

// ---------------------------------------------------------------------------
// Global scratch (no allocation allowed)
// ---------------------------------------------------------------------------
__device__ uint32_t g_qh[Bn*Hn*Wn*32], g_ql[Bn*Hn*Wn*32];
__device__ uint32_t g_kh[Bn*Hn*Wn*32], g_kl[Bn*Hn*Wn*32];
__device__ uint32_t g_vh[Bn*Hn*Wn*32], g_vl[Bn*Hn*Wn*32];
__device__ uint32_t g_xh[Bn*Hn*32*Wn], g_xl[Bn*Hn*32*Wn];
__device__ float g_attH[Bn*Wn*Hn*128];      // ((b*Wn + w)*Hn + h)*128 + g
__device__ float g_attW[Bn*Hn*Wn*128];      // ((b*Hn + h)*Wn + w)*128 + g
__device__ float g_oH[Bn*Hn*Wn*Cn];         // [b][w][h][c]
__device__ float g_oW[Bn*Hn*Wn*Cn];         // [b][h][w][c]
__device__ float2 g_msH[Bn*Hn*Wn];
__device__ float2 g_msW[Bn*Hn*Wn];
__device__ float2 g_ms[Bn*Hn*Wn];
__device__ __align__(16) char g_wb16[3*3*3*2*8192];

// ---------------------------------------------------------------------------
// helpers
// ---------------------------------------------------------------------------
__device__ __forceinline__ uint32_t smem_u32(const void* p) {
    uint32_t a;
    asm("{ .reg .u64 t; cvta.to.shared.u64 t, %1; cvt.u32.u64 %0, t; }"
        : "=r"(a) : "l"(p));
    return a;
}
__device__ __forceinline__ void ldsm4(uint32_t* r, uint32_t addr) {
    asm volatile("ldmatrix.sync.aligned.m8n8.x4.shared.b16 {%0,%1,%2,%3}, [%4];"
        : "=r"(r[0]), "=r"(r[1]), "=r"(r[2]), "=r"(r[3]) : "r"(addr));
}
__device__ __forceinline__ void mma16816(float (&d)[4], const uint32_t (&a)[4],
                                         uint32_t b0, uint32_t b1) {
    asm volatile("mma.sync.aligned.m16n8k16.row.col.f32.bf16.bf16.f32 "
        "{%0,%1,%2,%3}, {%4,%5,%6,%7}, {%8,%9}, {%0,%1,%2,%3};"
        : "+f"(d[0]), "+f"(d[1]), "+f"(d[2]), "+f"(d[3])
        : "r"(a[0]), "r"(a[1]), "r"(a[2]), "r"(a[3]), "r"(b0), "r"(b1));
}
__device__ __forceinline__ void split_pack(float a, float b,
                                           uint32_t& hp, uint32_t& lp) {
    __nv_bfloat16 ha = __float2bfloat16(a);
    __nv_bfloat16 hb = __float2bfloat16(b);
    __nv_bfloat16 la = __float2bfloat16(a - __bfloat162float(ha));
    __nv_bfloat16 lb = __float2bfloat16(b - __bfloat162float(hb));
    hp = ((uint32_t)__bfloat16_as_ushort(hb) << 16) | __bfloat16_as_ushort(ha);
    lp = ((uint32_t)__bfloat16_as_ushort(lb) << 16) | __bfloat16_as_ushort(la);
}

// ---------------------------------------------------------------------------
// Weight prep (unchanged)
// ---------------------------------------------------------------------------
__global__ void prep_w_k(const float* __restrict__ Wq,
                         const float* __restrict__ Wk,
                         const float* __restrict__ Wv)
{
    int i = blockIdx.x*blockDim.x + threadIdx.x;
    if (i >= 3*3*3*64*64) return;
    int ci = i & 63; int t = i >> 6;
    int co = t & 63; t >>= 6;
    int kx = t % 3;  t /= 3;
    int ky = t % 3;  t /= 3;
    int sel = t;
    const float* Ws = (sel == 0) ? Wq : ((sel == 1) ? Wk : Wv);
    float v = Ws[((co*Cn + ci)*3 + ky)*3 + kx];
    __nv_bfloat16 hi = __float2bfloat16(v);
    __nv_bfloat16 lo = __float2bfloat16(v - __bfloat162float(hi));
    size_t tbase = (size_t)(((sel*3 + ky)*3 + kx)*2)*8192;
    uint32_t off = (uint32_t)co*128 + (((uint32_t)ci*2) ^ (((uint32_t)co & 7) << 4));
    *(__nv_bfloat16*)(g_wb16 + tbase + off)        = hi;
    *(__nv_bfloat16*)(g_wb16 + tbase + 8192 + off) = lo;
}

// ---------------------------------------------------------------------------
// x pre-split: NCHW fp32 -> [b][h][cp][w] packed bf16 hi/lo
// ---------------------------------------------------------------------------
__global__ __launch_bounds__(256) void prep_x_k(const float* __restrict__ x)
{
    int id = blockIdx.x*256 + threadIdx.x;
    int w = id & 127, cp = (id >> 7) & 31, h = (id >> 12) & 127, b = id >> 19;
    float v0 = x[(((size_t)(b*64 + cp*2    ))*128 + h)*128 + w];
    float v1 = x[(((size_t)(b*64 + cp*2 + 1))*128 + h)*128 + w];
    uint32_t hp, lp;
    split_pack(v0, v1, hp, lp);
    g_xh[id] = hp;
    g_xl[id] = lp;
}

// ---------------------------------------------------------------------------
// Fused 3x3 conv via mma.sync — SOFTWARE PIPELINED:
// 4-slot A ring, register prefetch of row h+2 during compute of h, 1 sync/iter.
// Swizzle offsets precomputed per lane.
// ---------------------------------------------------------------------------
#define CONV_SMEM (73728 + 133120 + 128)

__global__ __launch_bounds__(256) void conv_mma_k(const float* __restrict__ bq,
                                                  const float* __restrict__ bk,
                                                  const float* __restrict__ bv)
{
    extern __shared__ char sm[];
    char* SW = sm;                     // 18 x 4096
    char* SA = sm + 73728;             // 8 x 16640  [slot*2 + split]
    float* sbias = (float*)(sm + 73728 + 133120);
    const int tid = threadIdx.x, lane = tid & 31, wid = tid >> 5;
    const int b = blockIdx.y;
    const int sel = blockIdx.z >> 1, co0 = (blockIdx.z & 1) * 32;
    const int h0 = blockIdx.x * 8;
    const float* bias = (sel == 0) ? bq : ((sel == 1) ? bk : bv);
    uint32_t* gh = (sel == 0) ? g_qh : ((sel == 1) ? g_kh : g_vh);
    uint32_t* gl = (sel == 0) ? g_ql : ((sel == 1) ? g_kl : g_vl);

    // Stage weights (18 half-co tiles)
    {
        const char* gw = g_wb16 + (size_t)sel*9*2*8192 + (size_t)co0*128;
        for (int i = tid; i < 18*256; i += 256) {
            int t = i >> 8, seg = i & 255;
            *(uint4*)(SW + t*4096 + seg*16) =
                *(const uint4*)(gw + (size_t)t*8192 + seg*16);
        }
    }
    if (tid < 32) sbias[tid] = bias[co0 + tid];
    // Zero boundary rows (w=-1 row 0, w=128 row 129) of all 8 slot-split tiles
    if (tid < 128) {
        int s8 = tid / 16, k = tid % 16;
        uint32_t off = s8*16640 + ((k < 8) ? 0u : 16512u) + (k & 7)*16;
        *(uint4*)(SA + off) = make_uint4(0,0,0,0);
    }

    // Prologue: stage rows h0-1, h0, h0+1
    for (int rr = -1; rr <= 1; rr++) {
        const int r = h0 + rr;
        const int s = (r + 4) & 3;
        char* hi = SA + (size_t)(s*2 + 0)*16640;
        char* lo = SA + (size_t)(s*2 + 1)*16640;
        const bool valid = ((unsigned)r < 128u);
        const uint32_t* xh = g_xh + (size_t)(b*Hn + (valid ? r : 0))*4096;
        const uint32_t* xl = g_xl + (size_t)(b*Hn + (valid ? r : 0))*4096;
#pragma unroll
        for (int j = 0; j < 16; j++) {
            int id = tid + j*256;
            int w = id & 127, cp = id >> 7;
            uint32_t hv = valid ? xh[id] : 0u;
            uint32_t lv = valid ? xl[id] : 0u;
            uint32_t row = (uint32_t)w + 1;
            uint32_t off = row*128 + (((uint32_t)cp*4) ^ ((row & 7) << 4));
            *(uint32_t*)(hi + off) = hv;
            *(uint32_t*)(lo + off) = lv;
        }
    }
    __syncthreads();

    const uint32_t SAb = smem_u32(SA);
    const uint32_t SWb = smem_u32(SW);
    const int m0 = wid * 16;
    const int aRowSel = lane & 15;
    const int aColSel = (lane & 16) ? 16 : 0;
    const int bRowSel = (lane & 7) + ((lane & 16) ? 8 : 0);
    const int bColSel = (lane & 8) ? 16 : 0;

    // Precompute lane-constant swizzled address offsets
    uint32_t aAO[3][4], bO[4];
#pragma unroll
    for (int kx = 0; kx < 3; kx++) {
        const int arow = m0 + kx + aRowSel;
        const uint32_t axor = ((uint32_t)arow & 7) << 4;
#pragma unroll
        for (int cc = 0; cc < 4; cc++)
            aAO[kx][cc] = (uint32_t)arow*128 + (((uint32_t)(cc*32 + aColSel)) ^ axor);
    }
    {
        const uint32_t bxor = ((uint32_t)bRowSel & 7) << 4;
#pragma unroll
        for (int cc = 0; cc < 4; cc++)
            bO[cc] = (uint32_t)bRowSel*128 + (((uint32_t)(cc*32 + bColSel)) ^ bxor);
    }

    for (int hh = 0; hh < 8; hh++) {
        const int h = h0 + hh;

        // Prefetch row h+2 into registers (hidden under compute)
        uint32_t ph[16], pl[16];
        const bool pf = (hh < 7);
        if (pf) {
            const int rn = h + 2;
            const bool valid = rn < 128;
            const uint32_t* xh = g_xh + (size_t)(b*Hn + (valid ? rn : 0))*4096;
            const uint32_t* xl = g_xl + (size_t)(b*Hn + (valid ? rn : 0))*4096;
#pragma unroll
            for (int j = 0; j < 16; j++) {
                int id = tid + j*256;
                ph[j] = valid ? xh[id] : 0u;
                pl[j] = valid ? xl[id] : 0u;
            }
        }

        float acc[4][4];
#pragma unroll
        for (int i = 0; i < 4; i++)
#pragma unroll
            for (int j = 0; j < 4; j++) acc[i][j] = 0.f;

#pragma unroll
        for (int ky = 0; ky < 3; ky++) {
            const int r = h + ky - 1;
            const int s = (r + 4) & 3;
            const uint32_t Ahi = SAb + (uint32_t)(s*2)*16640;
            const uint32_t Alo = Ahi + 16640;
#pragma unroll
            for (int kx = 0; kx < 3; kx++) {
                const uint32_t Wt = SWb + (uint32_t)((ky*3 + kx)*2)*4096;
#pragma unroll
                for (int cc = 0; cc < 4; cc++) {
                    uint32_t ah[4], al[4], bh[8], bl[8];
                    ldsm4(ah, Ahi + aAO[kx][cc]);
                    ldsm4(al, Alo + aAO[kx][cc]);
                    ldsm4(bh + 0, Wt + bO[cc]);
                    ldsm4(bh + 4, Wt + bO[cc] + 2048);
                    ldsm4(bl + 0, Wt + 4096 + bO[cc]);
                    ldsm4(bl + 4, Wt + 4096 + bO[cc] + 2048);
#pragma unroll
                    for (int nt = 0; nt < 4; nt++) {
                        mma16816(acc[nt], ah, bh[nt*2], bh[nt*2 + 1]);
                        mma16816(acc[nt], al, bh[nt*2], bh[nt*2 + 1]);
                        mma16816(acc[nt], ah, bl[nt*2], bl[nt*2 + 1]);
                    }
                }
            }
        }

        // Store prefetched row into free slot (h+2)&3, then single sync
        if (pf) {
            const int s = (h + 2 + 4) & 3;
            char* hi = SA + (size_t)(s*2 + 0)*16640;
            char* lo = SA + (size_t)(s*2 + 1)*16640;
#pragma unroll
            for (int j = 0; j < 16; j++) {
                int id = tid + j*256;
                int w = id & 127, cp = id >> 7;
                uint32_t row = (uint32_t)w + 1;
                uint32_t off = row*128 + (((uint32_t)cp*4) ^ ((row & 7) << 4));
                *(uint32_t*)(hi + off) = ph[j];
                *(uint32_t*)(lo + off) = pl[j];
            }
        }

        // Epilogue: packed bf16 hi/lo q/k/v
        const int wr = m0 + (lane >> 2);
        const int cb = (lane & 3) * 2;
        const size_t rowBase = (size_t)(b*Hn + h)*Wn;
#pragma unroll
        for (int nt = 0; nt < 4; nt++) {
            const int c = co0 + nt*8 + cb;
            const float b0 = sbias[nt*8 + cb], b1 = sbias[nt*8 + cb + 1];
            uint32_t hp, lp;
            split_pack(acc[nt][0] + b0, acc[nt][1] + b1, hp, lp);
            gh[(rowBase + wr)*32 + (c >> 1)] = hp;
            gl[(rowBase + wr)*32 + (c >> 1)] = lp;
            split_pack(acc[nt][2] + b0, acc[nt][3] + b1, hp, lp);
            gh[(rowBase + wr + 8)*32 + (c >> 1)] = hp;
            gl[(rowBase + wr + 8)*32 + (c >> 1)] = lp;
        }
        __syncthreads();
    }
}

// ---------------------------------------------------------------------------
// Logits via mma.sync (blockIdx.z: 0 = eH per (w,b), 1 = eW per (h,b)).
// ---------------------------------------------------------------------------
#define LOGITS_SMEM (4*16384)

__global__ __launch_bounds__(256) void logits_mma_k()
{
    extern __shared__ char sm[];
    char* QH = sm;            char* QL = sm + 16384;
    char* KH = sm + 32768;    char* KL = sm + 49152;
    const int tid = threadIdx.x, lane = tid & 31, wid = tid >> 5;
    const int p = blockIdx.x, b = blockIdx.y, mode = blockIdx.z;

    const size_t qkBase32 = mode ? (size_t)((b*Hn + p)*Wn)*32
                                 : (size_t)(b*Hn*Wn + p)*32;
    const int rowStr32 = mode ? 32 : Wn*32;

    for (int i = tid; i < 8192; i += 256) {
        int tsel = i >> 12, rem = i & 4095;
        int cp = rem & 31, r = rem >> 5;
        const uint32_t* sh = tsel ? g_kh : g_qh;
        const uint32_t* sl = tsel ? g_kl : g_ql;
        uint32_t hv = sh[qkBase32 + (size_t)r*rowStr32 + cp];
        uint32_t lv = sl[qkBase32 + (size_t)r*rowStr32 + cp];
        uint32_t off = (uint32_t)r*128 + (((uint32_t)cp*4) ^ (((uint32_t)r & 7) << 4));
        *(uint32_t*)((tsel ? KH : QH) + off) = hv;
        *(uint32_t*)((tsel ? KL : QL) + off) = lv;
    }
    __syncthreads();

    const uint32_t QHb = smem_u32(QH), QLb = smem_u32(QL);
    const uint32_t KHb = smem_u32(KH), KLb = smem_u32(KL);
    const int m0 = wid * 16;
    const int aRowSel = lane & 15;
    const int aColSel = (lane & 16) ? 16 : 0;
    const int bRowSel = (lane & 7) + ((lane & 16) ? 8 : 0);
    const int bColSel = (lane & 8) ? 16 : 0;

    // Precomputed swizzled offsets
    uint32_t aO[4], bO[4];
    {
        const int arow = m0 + aRowSel;
        const uint32_t axor = ((uint32_t)arow & 7) << 4;
        const uint32_t bxor = ((uint32_t)bRowSel & 7) << 4;
#pragma unroll
        for (int kc = 0; kc < 4; kc++) {
            aO[kc] = (uint32_t)arow*128 + (((uint32_t)(kc*32 + aColSel)) ^ axor);
            bO[kc] = (uint32_t)bRowSel*128 + (((uint32_t)(kc*32 + bColSel)) ^ bxor);
        }
    }

    float acc[16][4];
#pragma unroll
    for (int i = 0; i < 16; i++)
#pragma unroll
        for (int j = 0; j < 4; j++) acc[i][j] = 0.f;

#pragma unroll
    for (int kc = 0; kc < 4; kc++) {
        uint32_t ah[4], al[4];
        ldsm4(ah, QHb + aO[kc]);
        ldsm4(al, QLb + aO[kc]);
#pragma unroll
        for (int half = 0; half < 2; half++) {
            uint32_t bh[16], bl[16];
#pragma unroll
            for (int t = 0; t < 4; t++) {
                const uint32_t boff = bO[kc] + (uint32_t)(half*4 + t)*2048;
                ldsm4(bh + 4*t, KHb + boff);
                ldsm4(bl + 4*t, KLb + boff);
            }
#pragma unroll
            for (int nt = 0; nt < 8; nt++) {
                const int a = half*8 + nt;
                mma16816(acc[a], ah, bh[nt*2], bh[nt*2 + 1]);
                mma16816(acc[a], al, bh[nt*2], bh[nt*2 + 1]);
                mma16816(acc[a], ah, bl[nt*2], bl[nt*2 + 1]);
            }
        }
    }

    float* attOut = mode ? g_attW : g_attH;
    const size_t attBase = mode ? (size_t)((b*Hn + p)*Wn)*128
                                : (size_t)((b*Wn + p)*Hn)*128;
    const int msBase = mode ? (b*Hn + p)*Wn : b*Hn*Wn + p;
    const int msStr  = mode ? 1 : Wn;
    float2* msOut = mode ? g_msW : g_msH;

#pragma unroll
    for (int half2 = 0; half2 < 2; half2++) {
        const int row = m0 + (lane >> 2) + half2*8;
        float vals[32];
#pragma unroll
        for (int nt = 0; nt < 16; nt++) {
            const int g = nt*8 + (lane & 3)*2;
            float v0 = acc[nt][half2*2 + 0];
            float v1 = acc[nt][half2*2 + 1];
            if (!mode && row == g)     v0 = -CUDART_INF_F;
            if (!mode && row == g + 1) v1 = -CUDART_INF_F;
            *(float2*)&attOut[attBase + (size_t)row*128 + g] = make_float2(v0, v1);
            vals[nt*2] = v0; vals[nt*2 + 1] = v1;
        }
        float m = vals[0];
#pragma unroll
        for (int i = 1; i < 32; i++) m = fmaxf(m, vals[i]);
        m = fmaxf(m, __shfl_xor_sync(~0u, m, 1));
        m = fmaxf(m, __shfl_xor_sync(~0u, m, 2));
        float s = 0.f;
#pragma unroll
        for (int i = 0; i < 32; i++) s += __expf(vals[i] - m);
        s += __shfl_xor_sync(~0u, s, 1);
        s += __shfl_xor_sync(~0u, s, 2);
        if ((lane & 3) == 0) msOut[msBase + row*msStr] = make_float2(m, s);
    }
}

// ---------------------------------------------------------------------------
// Combine (max, sumexp) halves -> (max, 1/sum)
// ---------------------------------------------------------------------------
__global__ __launch_bounds__(256) void combine_ms_k()
{
    int i = blockIdx.x*256 + threadIdx.x;
    float2 a = g_msH[i], c = g_msW[i];
    float m = fmaxf(a.x, c.x);
    float s = a.y*__expf(a.x - m) + c.y*__expf(c.x - m);
    g_ms[i] = make_float2(m, 1.0f / s);
}

// ---------------------------------------------------------------------------
// Output GEMMs (blockIdx.z: 0 = out_W per (h,b), 1 = out_H per (w,b)).
// ---------------------------------------------------------------------------
#define OUT_SMEM (6*16384)

__global__ __launch_bounds__(256) void out_mma_k()
{
    extern __shared__ char sm[];
    char* AH0 = sm;            char* AH1 = sm + 16384;
    char* AL0 = sm + 32768;    char* AL1 = sm + 49152;
    char* VTH0 = sm + 65536;   char* VTH1 = sm + 73728;
    char* VTL0 = sm + 81920;   char* VTL1 = sm + 90112;
    const int tid = threadIdx.x, lane = tid & 31, wid = tid >> 5;
    const int p = blockIdx.x, b = blockIdx.y, mode = blockIdx.z;

    const float* attSrc = mode ? g_attH : g_attW;
    const size_t aBase = mode ? (size_t)((b*Wn + p)*Hn)*128
                              : (size_t)((b*Hn + p)*Wn)*128;
    const int msBase = mode ? b*Hn*Wn + p : (b*Hn + p)*Wn;
    const int msStr  = mode ? Wn : 1;
    const size_t vBase32 = mode ? (size_t)(b*Hn*Wn + p)*32
                                : (size_t)((b*Hn + p)*Wn)*32;
    const int vStr32 = mode ? Wn*32 : 32;
    float* oB = (mode ? g_oH : g_oW) + ((size_t)(b*Hn + p)*Wn)*Cn;

    for (int i = tid; i < 8192; i += 256) {
        int gp = i & 63, r = i >> 6;
        float2 ms = g_ms[msBase + r*msStr];
        float2 l = *(const float2*)&attSrc[aBase + (size_t)r*128 + gp*2];
        float e0 = __expf(l.x - ms.x)*ms.y;
        float e1 = __expf(l.y - ms.x)*ms.y;
        uint32_t hp, lp;
        split_pack(e0, e1, hp, lp);
        int t = gp >> 5, cp = gp & 31;
        uint32_t off = (uint32_t)r*128 + (((uint32_t)cp*4) ^ (((uint32_t)r & 7) << 4));
        *(uint32_t*)((t ? AH1 : AH0) + off) = hp;
        *(uint32_t*)((t ? AL1 : AL0) + off) = lp;
    }
    for (int i = tid; i < 4096; i += 256) {
        int cp = i & 31, g = i >> 5;
        uint32_t hv = g_vh[vBase32 + (size_t)g*vStr32 + cp];
        uint32_t lv = g_vl[vBase32 + (size_t)g*vStr32 + cp];
        int t = g >> 6, gin = g & 63;
        int c0 = cp*2, c1 = cp*2 + 1;
        uint32_t off0 = (uint32_t)c0*128 + (((uint32_t)gin*2) ^ (((uint32_t)c0 & 7) << 4));
        uint32_t off1 = (uint32_t)c1*128 + (((uint32_t)gin*2) ^ (((uint32_t)c1 & 7) << 4));
        *(uint16_t*)((t ? VTH1 : VTH0) + off0) = (uint16_t)(hv & 0xFFFF);
        *(uint16_t*)((t ? VTH1 : VTH0) + off1) = (uint16_t)(hv >> 16);
        *(uint16_t*)((t ? VTL1 : VTL0) + off0) = (uint16_t)(lv & 0xFFFF);
        *(uint16_t*)((t ? VTL1 : VTL0) + off1) = (uint16_t)(lv >> 16);
    }
    __syncthreads();

    const uint32_t AH0b = smem_u32(AH0), AH1b = smem_u32(AH1);
    const uint32_t AL0b = smem_u32(AL0), AL1b = smem_u32(AL1);
    const uint32_t VTH0b = smem_u32(VTH0), VTH1b = smem_u32(VTH1);
    const uint32_t VTL0b = smem_u32(VTL0), VTL1b = smem_u32(VTL1);
    const int m0 = wid * 16;
    const int aRowSel = lane & 15;
    const int aColSel = (lane & 16) ? 16 : 0;
    const int bRowSel = (lane & 7) + ((lane & 16) ? 8 : 0);
    const int bColSel = (lane & 8) ? 16 : 0;

    uint32_t aO[4], bO[4];
    {
        const int arow = m0 + aRowSel;
        const uint32_t axor = ((uint32_t)arow & 7) << 4;
        const uint32_t bxor = ((uint32_t)bRowSel & 7) << 4;
#pragma unroll
        for (int cc = 0; cc < 4; cc++) {
            aO[cc] = (uint32_t)arow*128 + (((uint32_t)(cc*32 + aColSel)) ^ axor);
            bO[cc] = (uint32_t)bRowSel*128 + (((uint32_t)(cc*32 + bColSel)) ^ bxor);
        }
    }

    float acc[8][4];
#pragma unroll
    for (int i = 0; i < 8; i++)
#pragma unroll
        for (int j = 0; j < 4; j++) acc[i][j] = 0.f;

#pragma unroll
    for (int kc = 0; kc < 8; kc++) {
        const uint32_t Ah = (kc < 4) ? AH0b : AH1b;
        const uint32_t Al = (kc < 4) ? AL0b : AL1b;
        const uint32_t Bh = (kc < 4) ? VTH0b : VTH1b;
        const uint32_t Bl = (kc < 4) ? VTL0b : VTL1b;
        const int cc = kc & 3;
        uint32_t ah[4], al[4];
        ldsm4(ah, Ah + aO[cc]);
        ldsm4(al, Al + aO[cc]);
        uint32_t bh[16], bl[16];
#pragma unroll
        for (int t = 0; t < 4; t++) {
            const uint32_t boff = bO[cc] + (uint32_t)t*2048;
            ldsm4(bh + 4*t, Bh + boff);
            ldsm4(bl + 4*t, Bl + boff);
        }
#pragma unroll
        for (int nt = 0; nt < 8; nt++) {
            mma16816(acc[nt], ah, bh[nt*2], bh[nt*2 + 1]);
            mma16816(acc[nt], al, bh[nt*2], bh[nt*2 + 1]);
            mma16816(acc[nt], ah, bl[nt*2], bl[nt*2 + 1]);
        }
    }

#pragma unroll
    for (int half2 = 0; half2 < 2; half2++) {
        const int row = m0 + (lane >> 2) + half2*8;
#pragma unroll
        for (int nt = 0; nt < 8; nt++) {
            const int c = nt*8 + (lane & 3)*2;
            *(float2*)&oB[(size_t)row*Cn + c] =
                make_float2(acc[nt][half2*2 + 0], acc[nt][half2*2 + 1]);
        }
    }
}

// ---------------------------------------------------------------------------
// Final: out[b][c][h][w] = gamma*(oH[b][w][h][c] + oW[b][h][w][c]) + x
// ---------------------------------------------------------------------------
__global__ __launch_bounds__(256) void final_k(const float* __restrict__ x,
                                               const float* __restrict__ gamma,
                                               float* __restrict__ out)
{
    __shared__ float s[Cn][33];
    const int w0 = blockIdx.x*32, h = blockIdx.y, b = blockIdx.z;
    const float g = gamma[0];
    for (int i = threadIdx.x; i < 32*Cn; i += 256) {
        int wl = i >> 6, c = i & 63;
        float a = g_oH[(((size_t)b*Wn + (w0+wl))*Hn + h)*Cn + c];
        float d = g_oW[(((size_t)b*Hn + h)*Wn + (w0+wl))*Cn + c];
        s[c][wl] = g*(a + d);
    }
    __syncthreads();
    for (int i = threadIdx.x; i < Cn*32; i += 256) {
        int c = i >> 5, wl = i & 31;
        size_t idx = (((size_t)b*Cn + c)*Hn + h)*Wn + w0 + wl;
        out[idx] = s[c][wl] + x[idx];
    }
}

// ---------------------------------------------------------------------------
extern "C" void kernel_launch(void* const* d_in, const int* in_sizes, int n_in,
                              void* d_out, int out_size)
{
    (void)in_sizes; (void)n_in; (void)out_size;
    const float* x     = (const float*)d_in[0];
    const float* Wq    = (const float*)d_in[1];
    const float* bq    = (const float*)d_in[2];
    const float* Wk    = (const float*)d_in[3];
    const float* bk    = (const float*)d_in[4];
    const float* Wv    = (const float*)d_in[5];
    const float* bv    = (const float*)d_in[6];
    const float* gamma = (const float*)d_in[7];
    float* out = (float*)d_out;

    static bool attr_set = false;
    if (!attr_set) {
        cudaFuncSetAttribute(conv_mma_k, cudaFuncAttributeMaxDynamicSharedMemorySize,
                             CONV_SMEM);
        cudaFuncSetAttribute(logits_mma_k, cudaFuncAttributeMaxDynamicSharedMemorySize,
                             LOGITS_SMEM);
        cudaFuncSetAttribute(out_mma_k, cudaFuncAttributeMaxDynamicSharedMemorySize,
                             OUT_SMEM);
        attr_set = true;
    }

    prep_w_k<<<(3*3*3*64*64 + 255)/256, 256>>>(Wq, Wk, Wv);
    prep_x_k<<<(Bn*Hn*32*Wn)/256, 256>>>(x);

    dim3 grid_conv(16, Bn, 6);   // (htile, b, sel*2 + co-half)
    conv_mma_k<<<grid_conv, 256, CONV_SMEM>>>(bq, bk, bv);

    dim3 grid_lg(128, Bn, 2);    // (p, b, mode)
    logits_mma_k<<<grid_lg, 256, LOGITS_SMEM>>>();

    combine_ms_k<<<(Bn*Hn*Wn)/256, 256>>>();

    out_mma_k<<<grid_lg, 256, OUT_SMEM>>>();

    dim3 grid_fin(Wn/32, Hn, Bn);
    final_k<<<grid_fin, 256>>>(x, gamma, out);
}